// round 11
// baseline (speedup 1.0000x reference)
#include <cuda_runtime.h>
#include <math.h>
#include <stdint.h>

#define LSEQ 384
#define DF 640

// Output packing: single(384*384) | pair(384*384*128) | dms(384) | shape(384)
#define OUT_SINGLE 0
#define OUT_PAIR   147456
#define OUT_DMS    19021824
#define OUT_SHAPE  19022208

// rows GEMM output columns: x1(0..319) | u(320..831) | hi(832..1343) | hj(1344..1855)
#define RSTRIDE 1856
#define U_OFF   320
#define HI_OFF  832
#define HJ_OFF  1344

__device__ float g_d[LSEQ];
__device__ float g_s[LSEQ];
__device__ __align__(16) float g_rows[LSEQ * RSTRIDE];
__device__ __align__(16) float g_uln[LSEQ * 512];
__device__ __align__(16) float g_ft[LSEQ * DF];
__device__ __align__(16) float g_wbig[DF * RSTRIDE];
__device__ __align__(16) float g_w2t[512 * 256];
__device__ __align__(16) float g_w3t[256 * 128];
__device__ __align__(16) float g_w4t[512 * 384];

// ---------------------------------------------------------------------------
// helpers
// ---------------------------------------------------------------------------
__device__ __forceinline__ uint32_t tf32r(float x) {
    uint32_t y;
    asm("cvt.rna.tf32.f32 %0, %1;" : "=r"(y) : "f"(x));
    return y;
}

__device__ __forceinline__ void mma_tf32(float* d, uint32_t a0, uint32_t a1,
                                         uint32_t a2, uint32_t a3,
                                         uint32_t b0, uint32_t b1) {
    asm volatile(
        "mma.sync.aligned.m16n8k8.row.col.f32.tf32.tf32.f32 "
        "{%0,%1,%2,%3}, {%4,%5,%6,%7}, {%8,%9}, {%0,%1,%2,%3};"
        : "+f"(d[0]), "+f"(d[1]), "+f"(d[2]), "+f"(d[3])
        : "r"(a0), "r"(a1), "r"(a2), "r"(a3), "r"(b0), "r"(b1));
}

__device__ __forceinline__ void cpasync16(void* dst, const void* src) {
    uint32_t d = (uint32_t)__cvta_generic_to_shared(dst);
    asm volatile("cp.async.ca.shared.global [%0], [%1], 16;" :: "r"(d), "l"(src));
}
__device__ __forceinline__ void cpcommit() {
    asm volatile("cp.async.commit_group;");
}
template <int N>
__device__ __forceinline__ void cpwait() {
    asm volatile("cp.async.wait_group %0;" :: "n"(N));
}

__device__ __forceinline__ void warp_red2(float& a, float& b) {
#pragma unroll
    for (int o = 16; o; o >>= 1) {
        a += __shfl_down_sync(0xffffffffu, a, o);
        b += __shfl_down_sync(0xffffffffu, b, o);
    }
}

__device__ __forceinline__ void block_stats(float psum, float psq, float n,
                                            volatile float* red, volatile float* mv) {
    warp_red2(psum, psq);
    int w = threadIdx.x >> 5, l = threadIdx.x & 31;
    if (l == 0) { red[w] = psum; red[8 + w] = psq; }
    __syncthreads();
    if (threadIdx.x == 0) {
        float s = 0.f, q = 0.f;
#pragma unroll
        for (int k = 0; k < 8; k++) { s += red[k]; q += red[8 + k]; }
        float m = s / n, v = q / n - m * m;
        mv[0] = m;
        mv[1] = rsqrtf(v + 1e-5f);
    }
    __syncthreads();
}

__device__ __forceinline__ float block_sum(float p, volatile float* red) {
    float z = 0.f;
    warp_red2(p, z);
    int w = threadIdx.x >> 5, l = threadIdx.x & 31;
    if (l == 0) red[w] = p;
    __syncthreads();
    if (threadIdx.x == 0) {
        float s = 0.f;
#pragma unroll
        for (int k = 0; k < 8; k++) s += red[k];
        red[0] = s;
    }
    __syncthreads();
    float s = red[0];
    __syncthreads();
    return s;
}

// ---------------------------------------------------------------------------
// prep: tf32-round all GEMM operands (linear layouts)
// ---------------------------------------------------------------------------
__global__ void prep_kernel(const float* __restrict__ feat,
                            const float* __restrict__ sp_w,
                            const float* __restrict__ ts_w1,
                            const float* __restrict__ ts_w2,
                            const float* __restrict__ tp_w1,
                            const float* __restrict__ tp_w2,
                            const float* __restrict__ tp_w3) {
    const int NF  = LSEQ * DF;
    const int NSP = DF * 320;
    const int NT1 = DF * 512;
    const int NWA = DF * 512;
    const int NWB = DF * 512;
    const int NT2 = 512 * 384;
    const int N2  = 512 * 256;
    const int N3  = 256 * 128;
    const int TOT = NF + NSP + NT1 + NWA + NWB + NT2 + N2 + N3;

    for (int t = blockIdx.x * blockDim.x + threadIdx.x; t < TOT;
         t += gridDim.x * blockDim.x) {
        int u = t;
        if (u < NF) { g_ft[u] = __uint_as_float(tf32r(feat[u])); continue; }
        u -= NF;
        if (u < NSP) {
            int k = u / 320, n = u % 320;
            g_wbig[k * RSTRIDE + n] = __uint_as_float(tf32r(sp_w[u]));
            continue;
        }
        u -= NSP;
        if (u < NT1) {
            int k = u / 512, n = u % 512;
            g_wbig[k * RSTRIDE + U_OFF + n] = __uint_as_float(tf32r(ts_w1[u]));
            continue;
        }
        u -= NT1;
        if (u < NWA) {
            int k = u / 512, n = u % 512;
            g_wbig[k * RSTRIDE + HI_OFF + n] = __uint_as_float(tf32r(tp_w1[u]));
            continue;
        }
        u -= NWA;
        if (u < NWB) {
            int k = u / 512, n = u % 512;
            g_wbig[k * RSTRIDE + HJ_OFF + n] = __uint_as_float(tf32r(tp_w1[(DF + k) * 512 + n]));
            continue;
        }
        u -= NWB;
        if (u < NT2) { g_w4t[u] = __uint_as_float(tf32r(ts_w2[u])); continue; }
        u -= NT2;
        if (u < N2) { g_w2t[u] = __uint_as_float(tf32r(tp_w2[u])); continue; }
        u -= N2;
        g_w3t[u] = __uint_as_float(tf32r(tp_w3[u]));
    }
}

// ---------------------------------------------------------------------------
// generic 64x64-tile tf32 GEMM body (used by gemm_rows/gemm_single)
// ---------------------------------------------------------------------------
#define GPADA 36
#define GPADB 72
#define ABUF (64 * GPADA)
#define BBUF (32 * GPADB)

struct GemmFrag { float acc[2][2][4]; };

template <int KDIM>
__device__ __forceinline__ void gemm_tile64(const float* __restrict__ Asrc, int lda,
                                            const float* __restrict__ Bsrc, int ldb,
                                            int i0, int n0,
                                            float* aS, float* bS, GemmFrag& fr) {
    const int tid = threadIdx.x;
    const int lane = tid & 31, warp = tid >> 5;
    const int wm = warp & 1, wn = warp >> 1;
    const int ar = wm * 32 + (lane >> 2);
    const int ak = lane & 3;
    const int bk = lane & 3;
    const int bn = lane >> 2;
    constexpr int NKB = KDIM / 32;

#pragma unroll
    for (int mt = 0; mt < 2; mt++)
#pragma unroll
        for (int nf = 0; nf < 2; nf++)
#pragma unroll
            for (int e = 0; e < 4; e++) fr.acc[mt][nf][e] = 0.f;

    for (int t = tid; t < 512; t += 256) {
        int r = t >> 3, c4 = t & 7;
        cpasync16(aS + r * GPADA + c4 * 4, Asrc + (size_t)(i0 + r) * lda + c4 * 4);
    }
    for (int t = tid; t < 512; t += 256) {
        int r = t >> 4, c4 = t & 15;
        cpasync16(bS + r * GPADB + c4 * 4, Bsrc + (size_t)r * ldb + n0 + c4 * 4);
    }
    cpcommit();

    for (int kb = 0; kb < NKB; kb++) {
        if (kb + 1 < NKB) {
            float* aD = aS + ((kb + 1) & 1) * ABUF;
            float* bD = bS + ((kb + 1) & 1) * BBUF;
            const float* aG = Asrc + (kb + 1) * 32;
            const float* bG = Bsrc + (size_t)(kb + 1) * 32 * ldb;
            for (int t = tid; t < 512; t += 256) {
                int r = t >> 3, c4 = t & 7;
                cpasync16(aD + r * GPADA + c4 * 4, aG + (size_t)(i0 + r) * lda + c4 * 4);
            }
            for (int t = tid; t < 512; t += 256) {
                int r = t >> 4, c4 = t & 15;
                cpasync16(bD + r * GPADB + c4 * 4, bG + (size_t)r * ldb + n0 + c4 * 4);
            }
            cpcommit();
            cpwait<1>();
        } else {
            cpwait<0>();
        }
        __syncthreads();
        const float* at = aS + (kb & 1) * ABUF;
        const float* bt = bS + (kb & 1) * BBUF;
#pragma unroll
        for (int k8 = 0; k8 < 4; k8++) {
            int kg = k8 * 8;
            uint32_t a[2][4];
#pragma unroll
            for (int mt = 0; mt < 2; mt++) {
                int r = ar + mt * 16;
                a[mt][0] = __float_as_uint(at[r * GPADA + kg + ak]);
                a[mt][1] = __float_as_uint(at[(r + 8) * GPADA + kg + ak]);
                a[mt][2] = __float_as_uint(at[r * GPADA + kg + ak + 4]);
                a[mt][3] = __float_as_uint(at[(r + 8) * GPADA + kg + ak + 4]);
            }
#pragma unroll
            for (int nf = 0; nf < 2; nf++) {
                int nc = wn * 16 + nf * 8 + bn;
                uint32_t b0 = __float_as_uint(bt[(kg + bk) * GPADB + nc]);
                uint32_t b1 = __float_as_uint(bt[(kg + bk + 4) * GPADB + nc]);
                mma_tf32(fr.acc[0][nf], a[0][0], a[0][1], a[0][2], a[0][3], b0, b1);
                mma_tf32(fr.acc[1][nf], a[1][0], a[1][1], a[1][2], a[1][3], b0, b1);
            }
        }
        __syncthreads();
    }
}

__global__ __launch_bounds__(256) void gemm_rows_kernel() {
    __shared__ float aS[2 * ABUF];
    __shared__ float bS[2 * BBUF];
    const int n0 = blockIdx.x * 64;
    const int i0 = blockIdx.y * 64;
    GemmFrag fr;
    gemm_tile64<DF>(g_ft, DF, g_wbig, RSTRIDE, i0, n0, aS, bS, fr);

    const int tid = threadIdx.x;
    const int lane = tid & 31, warp = tid >> 5;
    const int wm = warp & 1, wn = warp >> 1;
    const int ar = wm * 32 + (lane >> 2);
#pragma unroll
    for (int mt = 0; mt < 2; mt++) {
        int r = i0 + ar + mt * 16;
#pragma unroll
        for (int nf = 0; nf < 2; nf++) {
            int gc = n0 + wn * 16 + nf * 8 + 2 * (lane & 3);
            *(float2*)(g_rows + (size_t)r * RSTRIDE + gc) =
                make_float2(fr.acc[mt][nf][0], fr.acc[mt][nf][1]);
            *(float2*)(g_rows + (size_t)(r + 8) * RSTRIDE + gc) =
                make_float2(fr.acc[mt][nf][2], fr.acc[mt][nf][3]);
        }
    }
}

__global__ __launch_bounds__(256) void gemm_single_kernel(
    const float* __restrict__ ts_b2, float* __restrict__ out) {
    __shared__ float aS[2 * ABUF];
    __shared__ float bS[2 * BBUF];
    const int n0 = blockIdx.x * 64;
    const int i0 = blockIdx.y * 64;
    GemmFrag fr;
    gemm_tile64<512>(g_uln, 512, g_w4t, 384, i0, n0, aS, bS, fr);

    const int tid = threadIdx.x;
    const int lane = tid & 31, warp = tid >> 5;
    const int wm = warp & 1, wn = warp >> 1;
    const int ar = wm * 32 + (lane >> 2);
#pragma unroll
    for (int mt = 0; mt < 2; mt++) {
        int r = i0 + ar + mt * 16;
#pragma unroll
        for (int nf = 0; nf < 2; nf++) {
            int gc = n0 + wn * 16 + nf * 8 + 2 * (lane & 3);
            float bx = ts_b2[gc], by = ts_b2[gc + 1];
            *(float2*)(out + OUT_SINGLE + (size_t)r * 384 + gc) =
                make_float2(fr.acc[mt][nf][0] + bx, fr.acc[mt][nf][1] + by);
            *(float2*)(out + OUT_SINGLE + (size_t)(r + 8) * 384 + gc) =
                make_float2(fr.acc[mt][nf][2] + bx, fr.acc[mt][nf][3] + by);
        }
    }
}

// ---------------------------------------------------------------------------
// post_rows: per-row LN + small heads + uln production. 384 blocks.
// ---------------------------------------------------------------------------
__global__ __launch_bounds__(256) void post_rows_kernel(
    const float* __restrict__ sp_b, const float* __restrict__ sp_g,
    const float* __restrict__ sp_be,
    const float* __restrict__ dms_w1, const float* __restrict__ dms_b1,
    const float* __restrict__ dms_w2, const float* __restrict__ dms_b2,
    const float* __restrict__ sh_w1, const float* __restrict__ sh_b1,
    const float* __restrict__ sh_w2, const float* __restrict__ sh_b2,
    const float* __restrict__ ts_b1, const float* __restrict__ ts_g,
    const float* __restrict__ ts_be,
    float* __restrict__ out)
{
    __shared__ float sS[320];
    __shared__ float red[16];
    __shared__ float mv[2];

    const int i = blockIdx.x, tid = threadIdx.x;
    const float* rowp = g_rows + (size_t)i * RSTRIDE;

    float psum = 0.f, psq = 0.f;
    for (int c = tid; c < 320; c += 256) {
        float v = fmaxf(rowp[c] + sp_b[c], 0.f);
        sS[c] = v;
        psum += v;
        psq += v * v;
    }
    block_stats(psum, psq, 320.f, red, mv);
    {
        float m = mv[0], r = mv[1];
        for (int c = tid; c < 320; c += 256)
            sS[c] = (sS[c] - m) * r * sp_g[c] + sp_be[c];
    }
    __syncthreads();

    {
        float p = 0.f;
        if (tid < 160) {
            float acc = dms_b1[tid];
#pragma unroll 8
            for (int k = 0; k < 320; k++) acc = fmaf(sS[k], dms_w1[k * 160 + tid], acc);
            p = fmaxf(acc, 0.f) * dms_w2[tid];
        }
        float dsum = block_sum(p, red);
        if (tid == 0) {
            float v = dsum + dms_b2[0];
            g_d[i] = v;
            out[OUT_DMS + i] = v;
        }
    }
    __syncthreads();

    {
        float p = 0.f;
        if (tid < 160) {
            float acc = sh_b1[tid];
#pragma unroll 8
            for (int k = 0; k < 320; k++) acc = fmaf(sS[k], sh_w1[k * 160 + tid], acc);
            p = fmaxf(acc, 0.f) * sh_w2[tid];
        }
        float ssum = block_sum(p, red);
        if (tid == 0) {
            float v = ssum + sh_b2[0];
            g_s[i] = v;
            out[OUT_SHAPE + i] = v;
        }
    }

    float u0 = fmaxf(rowp[U_OFF + tid] + ts_b1[tid], 0.f);
    float u1 = fmaxf(rowp[U_OFF + tid + 256] + ts_b1[tid + 256], 0.f);
    psum = u0 + u1;
    psq = u0 * u0 + u1 * u1;
    block_stats(psum, psq, 512.f, red, mv);
    {
        float m = mv[0], r = mv[1];
        g_uln[(size_t)i * 512 + tid] =
            __uint_as_float(tf32r((u0 - m) * r * ts_g[tid] + ts_be[tid]));
        g_uln[(size_t)i * 512 + tid + 256] =
            __uint_as_float(tf32r((u1 - m) * r * ts_g[tid + 256] + ts_be[tid + 256]));
    }
}

// ---------------------------------------------------------------------------
// pair kernel: M=32 tiles, 102.7KB smem, 2 CTAs/SM, warp grid 1M x 8N
// ---------------------------------------------------------------------------
#define PADH  524   // hA row stride
#define PADH2 268   // h2 row stride
#define KT    16    // weight K-tile

#define OFF_H  0                      // hA: 32*524 = 16768
#define OFF_UN 16768                  // union: 2*4224 = 8448
#define OFF_MV 25216                  // 64
#define OFF_B2 25280                  // 256
#define OFF_B3 25536                  // 128
#define PAIR_SMEM_FLOATS 25664
#define PAIR_SMEM_BYTES  (PAIR_SMEM_FLOATS * 4)

#define PADW1 264
#define PADW2 136
#define W2BUF (KT * PADW1)   // 4224
#define W3BUF (KT * PADW2)   // 2176

__global__ __launch_bounds__(256, 2) void pair_kernel(
    const float* __restrict__ tp_w1, const float* __restrict__ tp_b1,
    const float* __restrict__ tp_g, const float* __restrict__ tp_be,
    const float* __restrict__ tp_b2, const float* __restrict__ tp_b3,
    float* __restrict__ out)
{
    extern __shared__ float sm[];
    float* hA  = sm + OFF_H;
    float* uS  = sm + OFF_UN;
    float* mvS = sm + OFF_MV;
    float* b2S = sm + OFF_B2;
    float* b3S = sm + OFF_B3;
    // stage-A overlay in union buffer 0
    float* hiS = uS;
    float* wcS = uS + 512;
    float* gS  = uS + 2560;
    float* beS = uS + 3072;

    const int i = blockIdx.y;
    const int j0 = blockIdx.x * 32;
    const int tid = threadIdx.x;
    const int lane = tid & 31, warp = tid >> 5;
    const int wn = warp;                 // N group 0..7

    // prefetch W2 tile 0 into union buffer 1 (disjoint from stage-A overlay)
    for (int t = tid; t < 1024; t += 256) {
        int r = t >> 6, c4 = t & 63;
        cpasync16(uS + W2BUF + r * PADW1 + c4 * 4, g_w2t + r * 256 + c4 * 4);
    }
    cpcommit();

    for (int c = tid; c < 512; c += 256) {
        hiS[c] = g_rows[(size_t)i * RSTRIDE + HI_OFF + c] + tp_b1[c];
        gS[c]  = tp_g[c];
        beS[c] = tp_be[c];
    }
    for (int c = tid; c < 2048; c += 256) wcS[c] = tp_w1[1280 * 512 + c];
    if (tid < 256) b2S[tid] = tp_b2[tid];
    if (tid < 128) b3S[tid] = tp_b3[tid];
    __syncthreads();

    // ---- stage A: h = relu(hi + hj + chem@Wc + b1), per-row stats ----
    const int jj = tid >> 3, sub = tid & 7;      // 32 rows x 8 threads
    const int j = j0 + jj;
    const float di = g_d[i], si = g_s[i];
    const float dj = g_d[j], sj = g_s[j];
    const float c0 = di - dj, c1 = di * dj, c2 = si - sj, c3 = si * sj;
    const float4* hj4 = (const float4*)(g_rows + (size_t)j * RSTRIDE + HJ_OFF);
    float* hrow = hA + jj * PADH;

    float psum = 0.f, psq = 0.f;
#pragma unroll 4
    for (int cc = 0; cc < 16; cc++) {
        int q = sub + 8 * cc;
        float4 v4 = hj4[q];
        int c = q * 4;
        float4 o;
        o.x = fmaxf(hiS[c]     + v4.x + c0 * wcS[c]     + c1 * wcS[512 + c]     + c2 * wcS[1024 + c]     + c3 * wcS[1536 + c],     0.f);
        o.y = fmaxf(hiS[c + 1] + v4.y + c0 * wcS[c + 1] + c1 * wcS[512 + c + 1] + c2 * wcS[1024 + c + 1] + c3 * wcS[1536 + c + 1], 0.f);
        o.z = fmaxf(hiS[c + 2] + v4.z + c0 * wcS[c + 2] + c1 * wcS[512 + c + 2] + c2 * wcS[1024 + c + 2] + c3 * wcS[1536 + c + 2], 0.f);
        o.w = fmaxf(hiS[c + 3] + v4.w + c0 * wcS[c + 3] + c1 * wcS[512 + c + 3] + c2 * wcS[1024 + c + 3] + c3 * wcS[1536 + c + 3], 0.f);
        psum += o.x + o.y + o.z + o.w;
        psq  += o.x * o.x + o.y * o.y + o.z * o.z + o.w * o.w;
        *(float4*)(hrow + c) = o;
    }
    psum += __shfl_down_sync(0xffffffffu, psum, 4, 8);
    psq  += __shfl_down_sync(0xffffffffu, psq, 4, 8);
    psum += __shfl_down_sync(0xffffffffu, psum, 2, 8);
    psq  += __shfl_down_sync(0xffffffffu, psq, 2, 8);
    psum += __shfl_down_sync(0xffffffffu, psum, 1, 8);
    psq  += __shfl_down_sync(0xffffffffu, psq, 1, 8);
    if (sub == 0) {
        float m = psum / 512.f;
        float v = psq / 512.f - m * m;
        mvS[2 * jj] = m;
        mvS[2 * jj + 1] = rsqrtf(v + 1e-5f);
    }
    __syncthreads();

    // LN + tf32 round
    {
        float m = mvS[2 * jj], r = mvS[2 * jj + 1];
#pragma unroll 4
        for (int cc = 0; cc < 16; cc++) {
            int c = (sub + 8 * cc) * 4;
            float4 v = *(float4*)(hrow + c);
            v.x = __uint_as_float(tf32r((v.x - m) * r * gS[c]     + beS[c]));
            v.y = __uint_as_float(tf32r((v.y - m) * r * gS[c + 1] + beS[c + 1]));
            v.z = __uint_as_float(tf32r((v.z - m) * r * gS[c + 2] + beS[c + 2]));
            v.w = __uint_as_float(tf32r((v.w - m) * r * gS[c + 3] + beS[c + 3]));
            *(float4*)(hrow + c) = v;
        }
    }
    __syncthreads();

    // ---- GEMM1: h2[32][256] = relu(lnh[32][512] @ W2 + b2), K-tiles of 16 ----
    float acc[2][4][4];
#pragma unroll
    for (int mt = 0; mt < 2; mt++)
#pragma unroll
        for (int nf = 0; nf < 4; nf++)
#pragma unroll
            for (int e = 0; e < 4; e++) acc[mt][nf][e] = 0.f;

    const int ar = lane >> 2;
    const int ak = lane & 3;
    const int bk = lane & 3;
    const int bn = lane >> 2;

    for (int kb = 0; kb < 32; kb++) {
        if (kb < 31) {
            float* dstB = uS + (kb & 1) * W2BUF;          // tile kb+1 buffer
            const float* srcB = g_w2t + (kb + 1) * KT * 256;
            for (int t = tid; t < 1024; t += 256) {
                int r = t >> 6, c4 = t & 63;
                cpasync16(dstB + r * PADW1 + c4 * 4, srcB + r * 256 + c4 * 4);
            }
            cpcommit();
            cpwait<1>();
        } else {
            cpwait<0>();
        }
        __syncthreads();
        const float* wt = uS + ((kb + 1) & 1) * W2BUF;    // tile kb
#pragma unroll
        for (int k8 = 0; k8 < 2; k8++) {
            int kcol = kb * KT + k8 * 8;
            uint32_t a[2][4];
#pragma unroll
            for (int mt = 0; mt < 2; mt++) {
                int r = ar + mt * 16;
                a[mt][0] = __float_as_uint(hA[r * PADH + kcol + ak]);
                a[mt][1] = __float_as_uint(hA[(r + 8) * PADH + kcol + ak]);
                a[mt][2] = __float_as_uint(hA[r * PADH + kcol + ak + 4]);
                a[mt][3] = __float_as_uint(hA[(r + 8) * PADH + kcol + ak + 4]);
            }
#pragma unroll
            for (int nf = 0; nf < 4; nf++) {
                int nc = wn * 32 + nf * 8 + bn;
                uint32_t b0 = __float_as_uint(wt[(k8 * 8 + bk) * PADW1 + nc]);
                uint32_t b1 = __float_as_uint(wt[(k8 * 8 + bk + 4) * PADW1 + nc]);
                mma_tf32(acc[0][nf], a[0][0], a[0][1], a[0][2], a[0][3], b0, b1);
                mma_tf32(acc[1][nf], a[1][0], a[1][1], a[1][2], a[1][3], b0, b1);
            }
        }
        __syncthreads();
    }

    // prefetch W3 tile 0 into W3 buffer 1 (overlaps epilogue1)
    for (int t = tid; t < 512; t += 256) {
        int r = t >> 5, c4 = t & 31;
        cpasync16(uS + W3BUF + r * PADW2 + c4 * 4, g_w3t + r * 128 + c4 * 4);
    }
    cpcommit();

    // epilogue1: bias + relu + tf32 -> h2 (overwrites hA region)
    float* h2 = hA;
#pragma unroll
    for (int mt = 0; mt < 2; mt++) {
        int r = ar + mt * 16;
#pragma unroll
        for (int nf = 0; nf < 4; nf++) {
            int cb = wn * 32 + nf * 8 + 2 * (lane & 3);
            float2 v0, v1;
            v0.x = __uint_as_float(tf32r(fmaxf(acc[mt][nf][0] + b2S[cb], 0.f)));
            v0.y = __uint_as_float(tf32r(fmaxf(acc[mt][nf][1] + b2S[cb + 1], 0.f)));
            v1.x = __uint_as_float(tf32r(fmaxf(acc[mt][nf][2] + b2S[cb], 0.f)));
            v1.y = __uint_as_float(tf32r(fmaxf(acc[mt][nf][3] + b2S[cb + 1], 0.f)));
            *(float2*)(h2 + r * PADH2 + cb) = v0;
            *(float2*)(h2 + (r + 8) * PADH2 + cb) = v1;
        }
    }
    __syncthreads();

    // ---- GEMM2: pair[32][128] = h2[32][256] @ W3 + b3, K-tiles of 16 ----
    float acc2[2][2][4];
#pragma unroll
    for (int mt = 0; mt < 2; mt++)
#pragma unroll
        for (int nf = 0; nf < 2; nf++)
#pragma unroll
            for (int e = 0; e < 4; e++) acc2[mt][nf][e] = 0.f;

    for (int kb = 0; kb < 16; kb++) {
        if (kb < 15) {
            float* dstB = uS + (kb & 1) * W3BUF;
            const float* srcB = g_w3t + (kb + 1) * KT * 128;
            for (int t = tid; t < 512; t += 256) {
                int r = t >> 5, c4 = t & 31;
                cpasync16(dstB + r * PADW2 + c4 * 4, srcB + r * 128 + c4 * 4);
            }
            cpcommit();
            cpwait<1>();
        } else {
            cpwait<0>();
        }
        __syncthreads();
        const float* wt = uS + ((kb + 1) & 1) * W3BUF;
#pragma unroll
        for (int k8 = 0; k8 < 2; k8++) {
            int kcol = kb * KT + k8 * 8;
            uint32_t a[2][4];
#pragma unroll
            for (int mt = 0; mt < 2; mt++) {
                int r = ar + mt * 16;
                a[mt][0] = __float_as_uint(h2[r * PADH2 + kcol + ak]);
                a[mt][1] = __float_as_uint(h2[(r + 8) * PADH2 + kcol + ak]);
                a[mt][2] = __float_as_uint(h2[r * PADH2 + kcol + ak + 4]);
                a[mt][3] = __float_as_uint(h2[(r + 8) * PADH2 + kcol + ak + 4]);
            }
#pragma unroll
            for (int nf = 0; nf < 2; nf++) {
                int nc = wn * 16 + nf * 8 + bn;
                uint32_t b0 = __float_as_uint(wt[(k8 * 8 + bk) * PADW2 + nc]);
                uint32_t b1 = __float_as_uint(wt[(k8 * 8 + bk + 4) * PADW2 + nc]);
                mma_tf32(acc2[0][nf], a[0][0], a[0][1], a[0][2], a[0][3], b0, b1);
                mma_tf32(acc2[1][nf], a[1][0], a[1][1], a[1][2], a[1][3], b0, b1);
            }
        }
        __syncthreads();
    }

    // epilogue2: bias + store
#pragma unroll
    for (int mt = 0; mt < 2; mt++) {
        int r = ar + mt * 16;
#pragma unroll
        for (int nf = 0; nf < 2; nf++) {
            int cb = wn * 16 + nf * 8 + 2 * (lane & 3);
            float2 v0, v1;
            v0.x = acc2[mt][nf][0] + b3S[cb];
            v0.y = acc2[mt][nf][1] + b3S[cb + 1];
            v1.x = acc2[mt][nf][2] + b3S[cb];
            v1.y = acc2[mt][nf][3] + b3S[cb + 1];
            size_t base0 = (size_t)OUT_PAIR + ((size_t)i * 384 + j0 + r) * 128 + cb;
            size_t base1 = (size_t)OUT_PAIR + ((size_t)i * 384 + j0 + r + 8) * 128 + cb;
            *(float2*)(out + base0) = v0;
            *(float2*)(out + base1) = v1;
        }
    }
}

extern "C" void kernel_launch(void* const* d_in, const int* in_sizes, int n_in,
                              void* d_out, int out_size) {
    const float* feat   = (const float*)d_in[0];
    const float* sp_w   = (const float*)d_in[1];
    const float* sp_b   = (const float*)d_in[2];
    const float* sp_g   = (const float*)d_in[3];
    const float* sp_be  = (const float*)d_in[4];
    const float* dms_w1 = (const float*)d_in[5];
    const float* dms_b1 = (const float*)d_in[6];
    const float* dms_w2 = (const float*)d_in[7];
    const float* dms_b2 = (const float*)d_in[8];
    const float* sh_w1  = (const float*)d_in[9];
    const float* sh_b1  = (const float*)d_in[10];
    const float* sh_w2  = (const float*)d_in[11];
    const float* sh_b2  = (const float*)d_in[12];
    const float* ts_w1  = (const float*)d_in[13];
    const float* ts_b1  = (const float*)d_in[14];
    const float* ts_g   = (const float*)d_in[15];
    const float* ts_be  = (const float*)d_in[16];
    const float* ts_w2  = (const float*)d_in[17];
    const float* ts_b2  = (const float*)d_in[18];
    const float* tp_w1  = (const float*)d_in[19];
    const float* tp_b1  = (const float*)d_in[20];
    const float* tp_g   = (const float*)d_in[21];
    const float* tp_be  = (const float*)d_in[22];
    const float* tp_w2  = (const float*)d_in[23];
    const float* tp_b2  = (const float*)d_in[24];
    const float* tp_w3  = (const float*)d_in[25];
    const float* tp_b3  = (const float*)d_in[26];
    float* out = (float*)d_out;

    cudaFuncSetAttribute(pair_kernel,
                         cudaFuncAttributeMaxDynamicSharedMemorySize,
                         PAIR_SMEM_BYTES);

    prep_kernel<<<256, 256>>>(feat, sp_w, ts_w1, ts_w2, tp_w1, tp_w2, tp_w3);

    gemm_rows_kernel<<<dim3(RSTRIDE / 64, LSEQ / 64), 256>>>();

    post_rows_kernel<<<LSEQ, 256>>>(sp_b, sp_g, sp_be,
                                    dms_w1, dms_b1, dms_w2, dms_b2,
                                    sh_w1, sh_b1, sh_w2, sh_b2,
                                    ts_b1, ts_g, ts_be, out);

    // pair as 4th launch (ncu profiling slot)
    pair_kernel<<<dim3(12, LSEQ), 256, PAIR_SMEM_BYTES>>>(
        tp_w1, tp_b1, tp_g, tp_be, tp_b2, tp_b3, out);

    gemm_single_kernel<<<dim3(384 / 64, LSEQ / 64), 256>>>(ts_b2, out);
}

// round 13
// speedup vs baseline: 1.6017x; 1.6017x over previous
#include <cuda_runtime.h>
#include <cuda_fp16.h>
#include <math.h>
#include <stdint.h>

#define LSEQ 384
#define DF 640

// Output packing: single(384*384) | pair(384*384*128) | dms(384) | shape(384)
#define OUT_SINGLE 0
#define OUT_PAIR   147456
#define OUT_DMS    19021824
#define OUT_SHAPE  19022208

// rows GEMM output columns: x1(0..319) | u(320..831) | hi(832..1343) | hj(1344..1855)
#define RSTRIDE 1856
#define U_OFF   320
#define HI_OFF  832
#define HJ_OFF  1344

__device__ float g_d[LSEQ];
__device__ float g_s[LSEQ];
__device__ __align__(16) float g_rows[LSEQ * RSTRIDE];
__device__ __align__(16) float g_uln[LSEQ * 512];
__device__ __align__(16) float g_ft[LSEQ * DF];
__device__ __align__(16) float g_wbig[DF * RSTRIDE];
__device__ __align__(16) float g_w4t[512 * 384];
// fp16 transposed pair weights: [N][K], half2 = adjacent K pair (m16n8k16 B frag)
__device__ __align__(16) __half g_w2h[256 * 512];
__device__ __align__(16) __half g_w3h[128 * 256];

// ---------------------------------------------------------------------------
// helpers
// ---------------------------------------------------------------------------
__device__ __forceinline__ uint32_t tf32r(float x) {
    uint32_t y;
    asm("cvt.rna.tf32.f32 %0, %1;" : "=r"(y) : "f"(x));
    return y;
}

__device__ __forceinline__ void mma_tf32(float* d, uint32_t a0, uint32_t a1,
                                         uint32_t a2, uint32_t a3,
                                         uint32_t b0, uint32_t b1) {
    asm volatile(
        "mma.sync.aligned.m16n8k8.row.col.f32.tf32.tf32.f32 "
        "{%0,%1,%2,%3}, {%4,%5,%6,%7}, {%8,%9}, {%0,%1,%2,%3};"
        : "+f"(d[0]), "+f"(d[1]), "+f"(d[2]), "+f"(d[3])
        : "r"(a0), "r"(a1), "r"(a2), "r"(a3), "r"(b0), "r"(b1));
}

// fp16 m16n8k16, fp32 accumulate
__device__ __forceinline__ void mma_f16(float* d, uint32_t a0, uint32_t a1,
                                        uint32_t a2, uint32_t a3,
                                        uint32_t b0, uint32_t b1) {
    asm volatile(
        "mma.sync.aligned.m16n8k16.row.col.f32.f16.f16.f32 "
        "{%0,%1,%2,%3}, {%4,%5,%6,%7}, {%8,%9}, {%0,%1,%2,%3};"
        : "+f"(d[0]), "+f"(d[1]), "+f"(d[2]), "+f"(d[3])
        : "r"(a0), "r"(a1), "r"(a2), "r"(a3), "r"(b0), "r"(b1));
}

__device__ __forceinline__ void cpasync16(void* dst, const void* src) {
    uint32_t d = (uint32_t)__cvta_generic_to_shared(dst);
    asm volatile("cp.async.ca.shared.global [%0], [%1], 16;" :: "r"(d), "l"(src));
}
__device__ __forceinline__ void cpcommit() {
    asm volatile("cp.async.commit_group;");
}
template <int N>
__device__ __forceinline__ void cpwait() {
    asm volatile("cp.async.wait_group %0;" :: "n"(N));
}

__device__ __forceinline__ void warp_red2(float& a, float& b) {
#pragma unroll
    for (int o = 16; o; o >>= 1) {
        a += __shfl_down_sync(0xffffffffu, a, o);
        b += __shfl_down_sync(0xffffffffu, b, o);
    }
}

__device__ __forceinline__ void block_stats(float psum, float psq, float n,
                                            volatile float* red, volatile float* mv) {
    warp_red2(psum, psq);
    int w = threadIdx.x >> 5, l = threadIdx.x & 31;
    if (l == 0) { red[w] = psum; red[8 + w] = psq; }
    __syncthreads();
    if (threadIdx.x == 0) {
        float s = 0.f, q = 0.f;
#pragma unroll
        for (int k = 0; k < 8; k++) { s += red[k]; q += red[8 + k]; }
        float m = s / n, v = q / n - m * m;
        mv[0] = m;
        mv[1] = rsqrtf(v + 1e-5f);
    }
    __syncthreads();
}

__device__ __forceinline__ float block_sum(float p, volatile float* red) {
    float z = 0.f;
    warp_red2(p, z);
    int w = threadIdx.x >> 5, l = threadIdx.x & 31;
    if (l == 0) red[w] = p;
    __syncthreads();
    if (threadIdx.x == 0) {
        float s = 0.f;
#pragma unroll
        for (int k = 0; k < 8; k++) s += red[k];
        red[0] = s;
    }
    __syncthreads();
    float s = red[0];
    __syncthreads();
    return s;
}

// ---------------------------------------------------------------------------
// prep: tf32-round rows/single operands; fp16-transpose pair weights
// ---------------------------------------------------------------------------
__global__ void prep_kernel(const float* __restrict__ feat,
                            const float* __restrict__ sp_w,
                            const float* __restrict__ ts_w1,
                            const float* __restrict__ ts_w2,
                            const float* __restrict__ tp_w1,
                            const float* __restrict__ tp_w2,
                            const float* __restrict__ tp_w3) {
    const int NF  = LSEQ * DF;
    const int NSP = DF * 320;
    const int NT1 = DF * 512;
    const int NWA = DF * 512;
    const int NWB = DF * 512;
    const int NT2 = 512 * 384;
    const int N2  = 512 * 256;
    const int N3  = 256 * 128;
    const int TOT = NF + NSP + NT1 + NWA + NWB + NT2 + N2 + N3;

    for (int t = blockIdx.x * blockDim.x + threadIdx.x; t < TOT;
         t += gridDim.x * blockDim.x) {
        int u = t;
        if (u < NF) { g_ft[u] = __uint_as_float(tf32r(feat[u])); continue; }
        u -= NF;
        if (u < NSP) {
            int k = u / 320, n = u % 320;
            g_wbig[k * RSTRIDE + n] = __uint_as_float(tf32r(sp_w[u]));
            continue;
        }
        u -= NSP;
        if (u < NT1) {
            int k = u / 512, n = u % 512;
            g_wbig[k * RSTRIDE + U_OFF + n] = __uint_as_float(tf32r(ts_w1[u]));
            continue;
        }
        u -= NT1;
        if (u < NWA) {
            int k = u / 512, n = u % 512;
            g_wbig[k * RSTRIDE + HI_OFF + n] = __uint_as_float(tf32r(tp_w1[u]));
            continue;
        }
        u -= NWA;
        if (u < NWB) {
            int k = u / 512, n = u % 512;
            g_wbig[k * RSTRIDE + HJ_OFF + n] = __uint_as_float(tf32r(tp_w1[(DF + k) * 512 + n]));
            continue;
        }
        u -= NWB;
        if (u < NT2) { g_w4t[u] = __uint_as_float(tf32r(ts_w2[u])); continue; }
        u -= NT2;
        if (u < N2) {
            int k = u / 256, n = u % 256;
            g_w2h[n * 512 + k] = __float2half_rn(tp_w2[u]);
            continue;
        }
        u -= N2;
        {
            int k = u / 128, n = u % 128;
            g_w3h[n * 256 + k] = __float2half_rn(tp_w3[u]);
        }
    }
}

// ---------------------------------------------------------------------------
// generic 64x64-tile tf32 GEMM body (used by gemm_rows/gemm_single)
// ---------------------------------------------------------------------------
#define GPADA 36
#define GPADB 72
#define ABUF (64 * GPADA)
#define BBUF (32 * GPADB)

struct GemmFrag { float acc[2][2][4]; };

template <int KDIM>
__device__ __forceinline__ void gemm_tile64(const float* __restrict__ Asrc, int lda,
                                            const float* __restrict__ Bsrc, int ldb,
                                            int i0, int n0,
                                            float* aS, float* bS, GemmFrag& fr) {
    const int tid = threadIdx.x;
    const int lane = tid & 31, warp = tid >> 5;
    const int wm = warp & 1, wn = warp >> 1;
    const int ar = wm * 32 + (lane >> 2);
    const int ak = lane & 3;
    const int bk = lane & 3;
    const int bn = lane >> 2;
    constexpr int NKB = KDIM / 32;

#pragma unroll
    for (int mt = 0; mt < 2; mt++)
#pragma unroll
        for (int nf = 0; nf < 2; nf++)
#pragma unroll
            for (int e = 0; e < 4; e++) fr.acc[mt][nf][e] = 0.f;

    for (int t = tid; t < 512; t += 256) {
        int r = t >> 3, c4 = t & 7;
        cpasync16(aS + r * GPADA + c4 * 4, Asrc + (size_t)(i0 + r) * lda + c4 * 4);
    }
    for (int t = tid; t < 512; t += 256) {
        int r = t >> 4, c4 = t & 15;
        cpasync16(bS + r * GPADB + c4 * 4, Bsrc + (size_t)r * ldb + n0 + c4 * 4);
    }
    cpcommit();

    for (int kb = 0; kb < NKB; kb++) {
        if (kb + 1 < NKB) {
            float* aD = aS + ((kb + 1) & 1) * ABUF;
            float* bD = bS + ((kb + 1) & 1) * BBUF;
            const float* aG = Asrc + (kb + 1) * 32;
            const float* bG = Bsrc + (size_t)(kb + 1) * 32 * ldb;
            for (int t = tid; t < 512; t += 256) {
                int r = t >> 3, c4 = t & 7;
                cpasync16(aD + r * GPADA + c4 * 4, aG + (size_t)(i0 + r) * lda + c4 * 4);
            }
            for (int t = tid; t < 512; t += 256) {
                int r = t >> 4, c4 = t & 15;
                cpasync16(bD + r * GPADB + c4 * 4, bG + (size_t)r * ldb + n0 + c4 * 4);
            }
            cpcommit();
            cpwait<1>();
        } else {
            cpwait<0>();
        }
        __syncthreads();
        const float* at = aS + (kb & 1) * ABUF;
        const float* bt = bS + (kb & 1) * BBUF;
#pragma unroll
        for (int k8 = 0; k8 < 4; k8++) {
            int kg = k8 * 8;
            uint32_t a[2][4];
#pragma unroll
            for (int mt = 0; mt < 2; mt++) {
                int r = ar + mt * 16;
                a[mt][0] = __float_as_uint(at[r * GPADA + kg + ak]);
                a[mt][1] = __float_as_uint(at[(r + 8) * GPADA + kg + ak]);
                a[mt][2] = __float_as_uint(at[r * GPADA + kg + ak + 4]);
                a[mt][3] = __float_as_uint(at[(r + 8) * GPADA + kg + ak + 4]);
            }
#pragma unroll
            for (int nf = 0; nf < 2; nf++) {
                int nc = wn * 16 + nf * 8 + bn;
                uint32_t b0 = __float_as_uint(bt[(kg + bk) * GPADB + nc]);
                uint32_t b1 = __float_as_uint(bt[(kg + bk + 4) * GPADB + nc]);
                mma_tf32(fr.acc[0][nf], a[0][0], a[0][1], a[0][2], a[0][3], b0, b1);
                mma_tf32(fr.acc[1][nf], a[1][0], a[1][1], a[1][2], a[1][3], b0, b1);
            }
        }
        __syncthreads();
    }
}

__global__ __launch_bounds__(256) void gemm_rows_kernel() {
    __shared__ float aS[2 * ABUF];
    __shared__ float bS[2 * BBUF];
    const int n0 = blockIdx.x * 64;
    const int i0 = blockIdx.y * 64;
    GemmFrag fr;
    gemm_tile64<DF>(g_ft, DF, g_wbig, RSTRIDE, i0, n0, aS, bS, fr);

    const int tid = threadIdx.x;
    const int lane = tid & 31, warp = tid >> 5;
    const int wm = warp & 1, wn = warp >> 1;
    const int ar = wm * 32 + (lane >> 2);
#pragma unroll
    for (int mt = 0; mt < 2; mt++) {
        int r = i0 + ar + mt * 16;
#pragma unroll
        for (int nf = 0; nf < 2; nf++) {
            int gc = n0 + wn * 16 + nf * 8 + 2 * (lane & 3);
            *(float2*)(g_rows + (size_t)r * RSTRIDE + gc) =
                make_float2(fr.acc[mt][nf][0], fr.acc[mt][nf][1]);
            *(float2*)(g_rows + (size_t)(r + 8) * RSTRIDE + gc) =
                make_float2(fr.acc[mt][nf][2], fr.acc[mt][nf][3]);
        }
    }
}

__global__ __launch_bounds__(256) void gemm_single_kernel(
    const float* __restrict__ ts_b2, float* __restrict__ out) {
    __shared__ float aS[2 * ABUF];
    __shared__ float bS[2 * BBUF];
    const int n0 = blockIdx.x * 64;
    const int i0 = blockIdx.y * 64;
    GemmFrag fr;
    gemm_tile64<512>(g_uln, 512, g_w4t, 384, i0, n0, aS, bS, fr);

    const int tid = threadIdx.x;
    const int lane = tid & 31, warp = tid >> 5;
    const int wm = warp & 1, wn = warp >> 1;
    const int ar = wm * 32 + (lane >> 2);
#pragma unroll
    for (int mt = 0; mt < 2; mt++) {
        int r = i0 + ar + mt * 16;
#pragma unroll
        for (int nf = 0; nf < 2; nf++) {
            int gc = n0 + wn * 16 + nf * 8 + 2 * (lane & 3);
            float bx = ts_b2[gc], by = ts_b2[gc + 1];
            *(float2*)(out + OUT_SINGLE + (size_t)r * 384 + gc) =
                make_float2(fr.acc[mt][nf][0] + bx, fr.acc[mt][nf][1] + by);
            *(float2*)(out + OUT_SINGLE + (size_t)(r + 8) * 384 + gc) =
                make_float2(fr.acc[mt][nf][2] + bx, fr.acc[mt][nf][3] + by);
        }
    }
}

// ---------------------------------------------------------------------------
// post_rows: per-row LN + small heads + uln production. 384 blocks.
// ---------------------------------------------------------------------------
__global__ __launch_bounds__(256) void post_rows_kernel(
    const float* __restrict__ sp_b, const float* __restrict__ sp_g,
    const float* __restrict__ sp_be,
    const float* __restrict__ dms_w1, const float* __restrict__ dms_b1,
    const float* __restrict__ dms_w2, const float* __restrict__ dms_b2,
    const float* __restrict__ sh_w1, const float* __restrict__ sh_b1,
    const float* __restrict__ sh_w2, const float* __restrict__ sh_b2,
    const float* __restrict__ ts_b1, const float* __restrict__ ts_g,
    const float* __restrict__ ts_be,
    float* __restrict__ out)
{
    __shared__ float sS[320];
    __shared__ float red[16];
    __shared__ float mv[2];

    const int i = blockIdx.x, tid = threadIdx.x;
    const float* rowp = g_rows + (size_t)i * RSTRIDE;

    float psum = 0.f, psq = 0.f;
    for (int c = tid; c < 320; c += 256) {
        float v = fmaxf(rowp[c] + sp_b[c], 0.f);
        sS[c] = v;
        psum += v;
        psq += v * v;
    }
    block_stats(psum, psq, 320.f, red, mv);
    {
        float m = mv[0], r = mv[1];
        for (int c = tid; c < 320; c += 256)
            sS[c] = (sS[c] - m) * r * sp_g[c] + sp_be[c];
    }
    __syncthreads();

    {
        float p = 0.f;
        if (tid < 160) {
            float acc = dms_b1[tid];
#pragma unroll 8
            for (int k = 0; k < 320; k++) acc = fmaf(sS[k], dms_w1[k * 160 + tid], acc);
            p = fmaxf(acc, 0.f) * dms_w2[tid];
        }
        float dsum = block_sum(p, red);
        if (tid == 0) {
            float v = dsum + dms_b2[0];
            g_d[i] = v;
            out[OUT_DMS + i] = v;
        }
    }
    __syncthreads();

    {
        float p = 0.f;
        if (tid < 160) {
            float acc = sh_b1[tid];
#pragma unroll 8
            for (int k = 0; k < 320; k++) acc = fmaf(sS[k], sh_w1[k * 160 + tid], acc);
            p = fmaxf(acc, 0.f) * sh_w2[tid];
        }
        float ssum = block_sum(p, red);
        if (tid == 0) {
            float v = ssum + sh_b2[0];
            g_s[i] = v;
            out[OUT_SHAPE + i] = v;
        }
    }

    float u0 = fmaxf(rowp[U_OFF + tid] + ts_b1[tid], 0.f);
    float u1 = fmaxf(rowp[U_OFF + tid + 256] + ts_b1[tid + 256], 0.f);
    psum = u0 + u1;
    psq = u0 * u0 + u1 * u1;
    block_stats(psum, psq, 512.f, red, mv);
    {
        float m = mv[0], r = mv[1];
        g_uln[(size_t)i * 512 + tid] =
            __uint_as_float(tf32r((u0 - m) * r * ts_g[tid] + ts_be[tid]));
        g_uln[(size_t)i * 512 + tid + 256] =
            __uint_as_float(tf32r((u1 - m) * r * ts_g[tid + 256] + ts_be[tid + 256]));
    }
}

// ---------------------------------------------------------------------------
// pair kernel: fp16 m16n8k16 HMMA. M=64 j-tile, 256 threads, warp grid 2M x 4N.
// smem floats: mv[128] | hiS[512] | wcS[2048] | gS[512] | beS[512] | b2S[256]
//   | b3S[128] | hA half2[64][260] (16640) | Wt 2 x [256][36] u32 (18432)
// ---------------------------------------------------------------------------
#define PK_MV  0
#define PK_HIS 128
#define PK_WCS 640
#define PK_GS  2688
#define PK_BES 3200
#define PK_B2S 3712
#define PK_B3S 3968
#define PK_HA  4096    // uint32 view, stride 260 per row
#define PK_WT  20736   // uint32 view, 2 buffers of 256*36
#define PK_FLOATS 39168
#define PK_BYTES (PK_FLOATS * 4)

#define HA_STRIDE 260
#define H2_STRIDE 132
#define WT1BUF (256 * 36)
#define WT2BUF (128 * 36)

__global__ __launch_bounds__(256, 1) void pair_kernel(
    const float* __restrict__ tp_w1, const float* __restrict__ tp_b1,
    const float* __restrict__ tp_g, const float* __restrict__ tp_be,
    const float* __restrict__ tp_b2, const float* __restrict__ tp_b3,
    float* __restrict__ out)
{
    extern __shared__ float sm[];
    uint32_t* hA = (uint32_t*)(sm + PK_HA);
    uint32_t* Wt = (uint32_t*)(sm + PK_WT);

    const int i = blockIdx.y;
    const int j0 = blockIdx.x * 64;
    const int tid = threadIdx.x;
    const int lane = tid & 31, warp = tid >> 5;
    const int wm = warp & 1, wn = warp >> 1;

    // prefetch W2 chunk 0 (cols 0..255, k2 0..31) into Wt buf0
    {
        const uint32_t* src = (const uint32_t*)g_w2h;
        for (int t = tid; t < 2048; t += 256) {
            int n = t >> 3, q = t & 7;
            cpasync16(Wt + n * 36 + q * 4, src + n * 256 + q * 4);
        }
        cpcommit();
    }

    for (int c = tid; c < 512; c += 256) {
        sm[PK_HIS + c] = g_rows[(size_t)i * RSTRIDE + HI_OFF + c] + tp_b1[c];
        sm[PK_GS + c]  = tp_g[c];
        sm[PK_BES + c] = tp_be[c];
    }
    for (int c = tid; c < 2048; c += 256) sm[PK_WCS + c] = tp_w1[1280 * 512 + c];
    if (tid < 256) sm[PK_B2S + tid] = tp_b2[tid];
    if (tid < 128) sm[PK_B3S + tid] = tp_b3[tid];
    __syncthreads();

    // ---- stage A pass 1: stats (recompute, no store) ----
    const int jj = tid >> 2, sub = tid & 3;
    const int j = j0 + jj;
    const float di = g_d[i], si = g_s[i];
    const float dj = g_d[j], sj = g_s[j];
    const float c0 = di - dj, c1 = di * dj, c2 = si - sj, c3 = si * sj;
    const float4* hj4 = (const float4*)(g_rows + (size_t)j * RSTRIDE + HJ_OFF);

    float psum = 0.f, psq = 0.f;
#pragma unroll 4
    for (int cc = 0; cc < 32; cc++) {
        int q = sub + 4 * cc;
        float4 v4 = hj4[q];
        int c = q * 4;
        float vin[4] = {v4.x, v4.y, v4.z, v4.w};
#pragma unroll
        for (int e = 0; e < 4; e++) {
            int cx = c + e;
            float v = fmaxf(sm[PK_HIS + cx] + vin[e] + c0 * sm[PK_WCS + cx]
                            + c1 * sm[PK_WCS + 512 + cx] + c2 * sm[PK_WCS + 1024 + cx]
                            + c3 * sm[PK_WCS + 1536 + cx], 0.f);
            psum += v;
            psq += v * v;
        }
    }
    psum += __shfl_down_sync(0xffffffffu, psum, 2, 4);
    psq  += __shfl_down_sync(0xffffffffu, psq, 2, 4);
    psum += __shfl_down_sync(0xffffffffu, psum, 1, 4);
    psq  += __shfl_down_sync(0xffffffffu, psq, 1, 4);
    if (sub == 0) {
        float m = psum / 512.f;
        float v = psq / 512.f - m * m;
        sm[PK_MV + 2 * jj] = m;
        sm[PK_MV + 2 * jj + 1] = rsqrtf(v + 1e-5f);
    }
    __syncthreads();

    // ---- stage A pass 2: recompute + LN + fp16 -> hA half2 ----
    {
        float m = sm[PK_MV + 2 * jj], r = sm[PK_MV + 2 * jj + 1];
#pragma unroll 4
        for (int cc = 0; cc < 32; cc++) {
            int q = sub + 4 * cc;
            float4 v4 = hj4[q];
            int c = q * 4;
            float vin[4] = {v4.x, v4.y, v4.z, v4.w};
            float o[4];
#pragma unroll
            for (int e = 0; e < 4; e++) {
                int cx = c + e;
                float v = fmaxf(sm[PK_HIS + cx] + vin[e] + c0 * sm[PK_WCS + cx]
                                + c1 * sm[PK_WCS + 512 + cx] + c2 * sm[PK_WCS + 1024 + cx]
                                + c3 * sm[PK_WCS + 1536 + cx], 0.f);
                o[e] = (v - m) * r * sm[PK_GS + cx] + sm[PK_BES + cx];
            }
            __half2 u0 = __floats2half2_rn(o[0], o[1]);
            __half2 u1 = __floats2half2_rn(o[2], o[3]);
            hA[jj * HA_STRIDE + (c >> 1)]     = *(uint32_t*)&u0;
            hA[jj * HA_STRIDE + (c >> 1) + 1] = *(uint32_t*)&u1;
        }
    }
    __syncthreads();

    // ---- GEMM1: h2[64][256] = relu(lnh[64][512] @ W2 + b2); K chunks of 64 ----
    float acc[2][8][4];
#pragma unroll
    for (int mt = 0; mt < 2; mt++)
#pragma unroll
        for (int nf = 0; nf < 8; nf++)
#pragma unroll
            for (int e = 0; e < 4; e++) acc[mt][nf][e] = 0.f;

    const int ar = wm * 32 + (lane >> 2);
    const int lk = lane & 3;
    const int bn = lane >> 2;

    for (int kc = 0; kc < 8; kc++) {
        if (kc < 7) {
            uint32_t* dstB = Wt + ((kc + 1) & 1) * WT1BUF;
            const uint32_t* src = (const uint32_t*)g_w2h + (kc + 1) * 32;
            for (int t = tid; t < 2048; t += 256) {
                int n = t >> 3, q = t & 7;
                cpasync16(dstB + n * 36 + q * 4, src + n * 256 + q * 4);
            }
            cpcommit();
            cpwait<1>();
        } else {
            cpwait<0>();
        }
        __syncthreads();
        const uint32_t* bt = Wt + (kc & 1) * WT1BUF;
#pragma unroll
        for (int s = 0; s < 4; s++) {
            int kg = kc * 32 + s * 8;   // half2 index base (global)
            uint32_t a[2][4];
#pragma unroll
            for (int mt = 0; mt < 2; mt++) {
                int r = ar + mt * 16;
                a[mt][0] = hA[r * HA_STRIDE + kg + lk];
                a[mt][1] = hA[(r + 8) * HA_STRIDE + kg + lk];
                a[mt][2] = hA[r * HA_STRIDE + kg + 4 + lk];
                a[mt][3] = hA[(r + 8) * HA_STRIDE + kg + 4 + lk];
            }
#pragma unroll
            for (int nf = 0; nf < 8; nf++) {
                int nc = wn * 64 + nf * 8 + bn;
                uint32_t b0 = bt[nc * 36 + s * 8 + lk];
                uint32_t b1 = bt[nc * 36 + s * 8 + 4 + lk];
                mma_f16(acc[0][nf], a[0][0], a[0][1], a[0][2], a[0][3], b0, b1);
                mma_f16(acc[1][nf], a[1][0], a[1][1], a[1][2], a[1][3], b0, b1);
            }
        }
        __syncthreads();
    }

    // prefetch W3 chunk 0 into Wt buf0 (overlaps epilogue1)
    {
        const uint32_t* src = (const uint32_t*)g_w3h;
        for (int t = tid; t < 1024; t += 256) {
            int n = t >> 3, q = t & 7;
            cpasync16(Wt + n * 36 + q * 4, src + n * 128 + q * 4);
        }
        cpcommit();
    }

    // epilogue1: bias + relu + fp16 -> h2 (reuse hA region, stride 132)
    uint32_t* h2 = hA;
    __syncthreads();   // all GEMM1 reads of hA done before overwrite
#pragma unroll
    for (int mt = 0; mt < 2; mt++) {
        int r = ar + mt * 16;
#pragma unroll
        for (int nf = 0; nf < 8; nf++) {
            int cb = wn * 64 + nf * 8 + 2 * lk;
            float x0 = fmaxf(acc[mt][nf][0] + sm[PK_B2S + cb], 0.f);
            float y0 = fmaxf(acc[mt][nf][1] + sm[PK_B2S + cb + 1], 0.f);
            float x1 = fmaxf(acc[mt][nf][2] + sm[PK_B2S + cb], 0.f);
            float y1 = fmaxf(acc[mt][nf][3] + sm[PK_B2S + cb + 1], 0.f);
            __half2 p0 = __floats2half2_rn(x0, y0);
            __half2 p1 = __floats2half2_rn(x1, y1);
            h2[r * H2_STRIDE + (cb >> 1)]       = *(uint32_t*)&p0;
            h2[(r + 8) * H2_STRIDE + (cb >> 1)] = *(uint32_t*)&p1;
        }
    }
    __syncthreads();

    // ---- GEMM2: pair[64][128] = h2[64][256] @ W3 + b3; K chunks of 64 ----
    float acc2[2][4][4];
#pragma unroll
    for (int mt = 0; mt < 2; mt++)
#pragma unroll
        for (int nf = 0; nf < 4; nf++)
#pragma unroll
            for (int e = 0; e < 4; e++) acc2[mt][nf][e] = 0.f;

    for (int kc = 0; kc < 4; kc++) {
        if (kc < 3) {
            uint32_t* dstB = Wt + ((kc + 1) & 1) * WT2BUF;
            const uint32_t* src = (const uint32_t*)g_w3h + (kc + 1) * 32;
            for (int t = tid; t < 1024; t += 256) {
                int n = t >> 3, q = t & 7;
                cpasync16(dstB + n * 36 + q * 4, src + n * 128 + q * 4);
            }
            cpcommit();
            cpwait<1>();
        } else {
            cpwait<0>();
        }
        __syncthreads();
        const uint32_t* bt = Wt + (kc & 1) * WT2BUF;
#pragma unroll
        for (int s = 0; s < 4; s++) {
            int kg = kc * 32 + s * 8;
            uint32_t a[2][4];
#pragma unroll
            for (int mt = 0; mt < 2; mt++) {
                int r = ar + mt * 16;
                a[mt][0] = h2[r * H2_STRIDE + kg + lk];
                a[mt][1] = h2[(r + 8) * H2_STRIDE + kg + lk];
                a[mt][2] = h2[r * H2_STRIDE + kg + 4 + lk];
                a[mt][3] = h2[(r + 8) * H2_STRIDE + kg + 4 + lk];
            }
#pragma unroll
            for (int nf = 0; nf < 4; nf++) {
                int nc = wn * 32 + nf * 8 + bn;
                uint32_t b0 = bt[nc * 36 + s * 8 + lk];
                uint32_t b1 = bt[nc * 36 + s * 8 + 4 + lk];
                mma_f16(acc2[0][nf], a[0][0], a[0][1], a[0][2], a[0][3], b0, b1);
                mma_f16(acc2[1][nf], a[1][0], a[1][1], a[1][2], a[1][3], b0, b1);
            }
        }
        __syncthreads();
    }

    // epilogue2: bias + store
#pragma unroll
    for (int mt = 0; mt < 2; mt++) {
        int r = ar + mt * 16;
#pragma unroll
        for (int nf = 0; nf < 4; nf++) {
            int cb = wn * 32 + nf * 8 + 2 * lk;
            float2 v0, v1;
            v0.x = acc2[mt][nf][0] + sm[PK_B3S + cb];
            v0.y = acc2[mt][nf][1] + sm[PK_B3S + cb + 1];
            v1.x = acc2[mt][nf][2] + sm[PK_B3S + cb];
            v1.y = acc2[mt][nf][3] + sm[PK_B3S + cb + 1];
            size_t base0 = (size_t)OUT_PAIR + ((size_t)i * 384 + j0 + r) * 128 + cb;
            size_t base1 = (size_t)OUT_PAIR + ((size_t)i * 384 + j0 + r + 8) * 128 + cb;
            *(float2*)(out + base0) = v0;
            *(float2*)(out + base1) = v1;
        }
    }
}

extern "C" void kernel_launch(void* const* d_in, const int* in_sizes, int n_in,
                              void* d_out, int out_size) {
    const float* feat   = (const float*)d_in[0];
    const float* sp_w   = (const float*)d_in[1];
    const float* sp_b   = (const float*)d_in[2];
    const float* sp_g   = (const float*)d_in[3];
    const float* sp_be  = (const float*)d_in[4];
    const float* dms_w1 = (const float*)d_in[5];
    const float* dms_b1 = (const float*)d_in[6];
    const float* dms_w2 = (const float*)d_in[7];
    const float* dms_b2 = (const float*)d_in[8];
    const float* sh_w1  = (const float*)d_in[9];
    const float* sh_b1  = (const float*)d_in[10];
    const float* sh_w2  = (const float*)d_in[11];
    const float* sh_b2  = (const float*)d_in[12];
    const float* ts_w1  = (const float*)d_in[13];
    const float* ts_b1  = (const float*)d_in[14];
    const float* ts_g   = (const float*)d_in[15];
    const float* ts_be  = (const float*)d_in[16];
    const float* ts_w2  = (const float*)d_in[17];
    const float* ts_b2  = (const float*)d_in[18];
    const float* tp_w1  = (const float*)d_in[19];
    const float* tp_b1  = (const float*)d_in[20];
    const float* tp_g   = (const float*)d_in[21];
    const float* tp_be  = (const float*)d_in[22];
    const float* tp_w2  = (const float*)d_in[23];
    const float* tp_b2  = (const float*)d_in[24];
    const float* tp_w3  = (const float*)d_in[25];
    const float* tp_b3  = (const float*)d_in[26];
    float* out = (float*)d_out;

    cudaFuncSetAttribute(pair_kernel,
                         cudaFuncAttributeMaxDynamicSharedMemorySize,
                         PK_BYTES);

    prep_kernel<<<256, 256>>>(feat, sp_w, ts_w1, ts_w2, tp_w1, tp_w2, tp_w3);

    gemm_rows_kernel<<<dim3(RSTRIDE / 64, LSEQ / 64), 256>>>();

    post_rows_kernel<<<LSEQ, 256>>>(sp_b, sp_g, sp_be,
                                    dms_w1, dms_b1, dms_w2, dms_b2,
                                    sh_w1, sh_b1, sh_w2, sh_b2,
                                    ts_b1, ts_g, ts_be, out);

    // pair as 4th launch (ncu profiling slot)
    pair_kernel<<<dim3(6, LSEQ), 256, PK_BYTES>>>(
        tp_w1, tp_b1, tp_g, tp_be, tp_b2, tp_b3, out);

    gemm_single_kernel<<<dim3(384 / 64, LSEQ / 64), 256>>>(ts_b2, out);
}

// round 14
// speedup vs baseline: 1.6369x; 1.0219x over previous
#include <cuda_runtime.h>
#include <cuda_fp16.h>
#include <math.h>
#include <stdint.h>

#define LSEQ 384
#define DF 640

// Output packing: single(384*384) | pair(384*384*128) | dms(384) | shape(384)
#define OUT_SINGLE 0
#define OUT_PAIR   147456
#define OUT_DMS    19021824
#define OUT_SHAPE  19022208

// rows GEMM output columns: x1(0..319) | u(320..831) | hi(832..1343) | hj(1344..1855)
#define RSTRIDE 1856
#define U_OFF   320
#define HI_OFF  832
#define HJ_OFF  1344

__device__ float g_d[LSEQ];
__device__ float g_s[LSEQ];
__device__ __align__(16) float g_rows[LSEQ * RSTRIDE];
__device__ __align__(16) float g_uln[LSEQ * 512];
__device__ __align__(16) float g_ft[LSEQ * DF];
__device__ __align__(16) float g_wbig[DF * RSTRIDE];
__device__ __align__(16) float g_w4t[512 * 384];
// fp16 transposed pair weights: [N][K], half2 = adjacent K pair (m16n8k16 B frag)
__device__ __align__(16) __half g_w2h[256 * 512];
__device__ __align__(16) __half g_w3h[128 * 256];

// ---------------------------------------------------------------------------
// helpers
// ---------------------------------------------------------------------------
__device__ __forceinline__ uint32_t tf32r(float x) {
    uint32_t y;
    asm("cvt.rna.tf32.f32 %0, %1;" : "=r"(y) : "f"(x));
    return y;
}

__device__ __forceinline__ void mma_tf32(float* d, uint32_t a0, uint32_t a1,
                                         uint32_t a2, uint32_t a3,
                                         uint32_t b0, uint32_t b1) {
    asm volatile(
        "mma.sync.aligned.m16n8k8.row.col.f32.tf32.tf32.f32 "
        "{%0,%1,%2,%3}, {%4,%5,%6,%7}, {%8,%9}, {%0,%1,%2,%3};"
        : "+f"(d[0]), "+f"(d[1]), "+f"(d[2]), "+f"(d[3])
        : "r"(a0), "r"(a1), "r"(a2), "r"(a3), "r"(b0), "r"(b1));
}

// fp16 m16n8k16, fp32 accumulate
__device__ __forceinline__ void mma_f16(float* d, uint32_t a0, uint32_t a1,
                                        uint32_t a2, uint32_t a3,
                                        uint32_t b0, uint32_t b1) {
    asm volatile(
        "mma.sync.aligned.m16n8k16.row.col.f32.f16.f16.f32 "
        "{%0,%1,%2,%3}, {%4,%5,%6,%7}, {%8,%9}, {%0,%1,%2,%3};"
        : "+f"(d[0]), "+f"(d[1]), "+f"(d[2]), "+f"(d[3])
        : "r"(a0), "r"(a1), "r"(a2), "r"(a3), "r"(b0), "r"(b1));
}

__device__ __forceinline__ void cpasync16(void* dst, const void* src) {
    uint32_t d = (uint32_t)__cvta_generic_to_shared(dst);
    asm volatile("cp.async.ca.shared.global [%0], [%1], 16;" :: "r"(d), "l"(src));
}
__device__ __forceinline__ void cpcommit() {
    asm volatile("cp.async.commit_group;");
}
template <int N>
__device__ __forceinline__ void cpwait() {
    asm volatile("cp.async.wait_group %0;" :: "n"(N));
}

__device__ __forceinline__ void warp_red2(float& a, float& b) {
#pragma unroll
    for (int o = 16; o; o >>= 1) {
        a += __shfl_down_sync(0xffffffffu, a, o);
        b += __shfl_down_sync(0xffffffffu, b, o);
    }
}

__device__ __forceinline__ void block_stats(float psum, float psq, float n,
                                            volatile float* red, volatile float* mv) {
    warp_red2(psum, psq);
    int w = threadIdx.x >> 5, l = threadIdx.x & 31;
    if (l == 0) { red[w] = psum; red[8 + w] = psq; }
    __syncthreads();
    if (threadIdx.x == 0) {
        float s = 0.f, q = 0.f;
#pragma unroll
        for (int k = 0; k < 8; k++) { s += red[k]; q += red[8 + k]; }
        float m = s / n, v = q / n - m * m;
        mv[0] = m;
        mv[1] = rsqrtf(v + 1e-5f);
    }
    __syncthreads();
}

__device__ __forceinline__ float block_sum(float p, volatile float* red) {
    float z = 0.f;
    warp_red2(p, z);
    int w = threadIdx.x >> 5, l = threadIdx.x & 31;
    if (l == 0) red[w] = p;
    __syncthreads();
    if (threadIdx.x == 0) {
        float s = 0.f;
#pragma unroll
        for (int k = 0; k < 8; k++) s += red[k];
        red[0] = s;
    }
    __syncthreads();
    float s = red[0];
    __syncthreads();
    return s;
}

// ---------------------------------------------------------------------------
// prep: tf32-round rows/single operands; fp16-transpose pair weights
// ---------------------------------------------------------------------------
__global__ void prep_kernel(const float* __restrict__ feat,
                            const float* __restrict__ sp_w,
                            const float* __restrict__ ts_w1,
                            const float* __restrict__ ts_w2,
                            const float* __restrict__ tp_w1,
                            const float* __restrict__ tp_w2,
                            const float* __restrict__ tp_w3) {
    const int NF  = LSEQ * DF;
    const int NSP = DF * 320;
    const int NT1 = DF * 512;
    const int NWA = DF * 512;
    const int NWB = DF * 512;
    const int NT2 = 512 * 384;
    const int N2  = 512 * 256;
    const int N3  = 256 * 128;
    const int TOT = NF + NSP + NT1 + NWA + NWB + NT2 + N2 + N3;

    for (int t = blockIdx.x * blockDim.x + threadIdx.x; t < TOT;
         t += gridDim.x * blockDim.x) {
        int u = t;
        if (u < NF) { g_ft[u] = __uint_as_float(tf32r(feat[u])); continue; }
        u -= NF;
        if (u < NSP) {
            int k = u / 320, n = u % 320;
            g_wbig[k * RSTRIDE + n] = __uint_as_float(tf32r(sp_w[u]));
            continue;
        }
        u -= NSP;
        if (u < NT1) {
            int k = u / 512, n = u % 512;
            g_wbig[k * RSTRIDE + U_OFF + n] = __uint_as_float(tf32r(ts_w1[u]));
            continue;
        }
        u -= NT1;
        if (u < NWA) {
            int k = u / 512, n = u % 512;
            g_wbig[k * RSTRIDE + HI_OFF + n] = __uint_as_float(tf32r(tp_w1[u]));
            continue;
        }
        u -= NWA;
        if (u < NWB) {
            int k = u / 512, n = u % 512;
            g_wbig[k * RSTRIDE + HJ_OFF + n] = __uint_as_float(tf32r(tp_w1[(DF + k) * 512 + n]));
            continue;
        }
        u -= NWB;
        if (u < NT2) { g_w4t[u] = __uint_as_float(tf32r(ts_w2[u])); continue; }
        u -= NT2;
        if (u < N2) {
            int k = u / 256, n = u % 256;
            g_w2h[n * 512 + k] = __float2half_rn(tp_w2[u]);
            continue;
        }
        u -= N2;
        {
            int k = u / 128, n = u % 128;
            g_w3h[n * 256 + k] = __float2half_rn(tp_w3[u]);
        }
    }
}

// ---------------------------------------------------------------------------
// generic 64x64-tile tf32 GEMM body (used by gemm_rows/gemm_single)
// ---------------------------------------------------------------------------
#define GPADA 36
#define GPADB 72
#define ABUF (64 * GPADA)
#define BBUF (32 * GPADB)

struct GemmFrag { float acc[2][2][4]; };

template <int KDIM>
__device__ __forceinline__ void gemm_tile64(const float* __restrict__ Asrc, int lda,
                                            const float* __restrict__ Bsrc, int ldb,
                                            int i0, int n0,
                                            float* aS, float* bS, GemmFrag& fr) {
    const int tid = threadIdx.x;
    const int lane = tid & 31, warp = tid >> 5;
    const int wm = warp & 1, wn = warp >> 1;
    const int ar = wm * 32 + (lane >> 2);
    const int ak = lane & 3;
    const int bk = lane & 3;
    const int bn = lane >> 2;
    constexpr int NKB = KDIM / 32;

#pragma unroll
    for (int mt = 0; mt < 2; mt++)
#pragma unroll
        for (int nf = 0; nf < 2; nf++)
#pragma unroll
            for (int e = 0; e < 4; e++) fr.acc[mt][nf][e] = 0.f;

    for (int t = tid; t < 512; t += 256) {
        int r = t >> 3, c4 = t & 7;
        cpasync16(aS + r * GPADA + c4 * 4, Asrc + (size_t)(i0 + r) * lda + c4 * 4);
    }
    for (int t = tid; t < 512; t += 256) {
        int r = t >> 4, c4 = t & 15;
        cpasync16(bS + r * GPADB + c4 * 4, Bsrc + (size_t)r * ldb + n0 + c4 * 4);
    }
    cpcommit();

    for (int kb = 0; kb < NKB; kb++) {
        if (kb + 1 < NKB) {
            float* aD = aS + ((kb + 1) & 1) * ABUF;
            float* bD = bS + ((kb + 1) & 1) * BBUF;
            const float* aG = Asrc + (kb + 1) * 32;
            const float* bG = Bsrc + (size_t)(kb + 1) * 32 * ldb;
            for (int t = tid; t < 512; t += 256) {
                int r = t >> 3, c4 = t & 7;
                cpasync16(aD + r * GPADA + c4 * 4, aG + (size_t)(i0 + r) * lda + c4 * 4);
            }
            for (int t = tid; t < 512; t += 256) {
                int r = t >> 4, c4 = t & 15;
                cpasync16(bD + r * GPADB + c4 * 4, bG + (size_t)r * ldb + n0 + c4 * 4);
            }
            cpcommit();
            cpwait<1>();
        } else {
            cpwait<0>();
        }
        __syncthreads();
        const float* at = aS + (kb & 1) * ABUF;
        const float* bt = bS + (kb & 1) * BBUF;
#pragma unroll
        for (int k8 = 0; k8 < 4; k8++) {
            int kg = k8 * 8;
            uint32_t a[2][4];
#pragma unroll
            for (int mt = 0; mt < 2; mt++) {
                int r = ar + mt * 16;
                a[mt][0] = __float_as_uint(at[r * GPADA + kg + ak]);
                a[mt][1] = __float_as_uint(at[(r + 8) * GPADA + kg + ak]);
                a[mt][2] = __float_as_uint(at[r * GPADA + kg + ak + 4]);
                a[mt][3] = __float_as_uint(at[(r + 8) * GPADA + kg + ak + 4]);
            }
#pragma unroll
            for (int nf = 0; nf < 2; nf++) {
                int nc = wn * 16 + nf * 8 + bn;
                uint32_t b0 = __float_as_uint(bt[(kg + bk) * GPADB + nc]);
                uint32_t b1 = __float_as_uint(bt[(kg + bk + 4) * GPADB + nc]);
                mma_tf32(fr.acc[0][nf], a[0][0], a[0][1], a[0][2], a[0][3], b0, b1);
                mma_tf32(fr.acc[1][nf], a[1][0], a[1][1], a[1][2], a[1][3], b0, b1);
            }
        }
        __syncthreads();
    }
}

__global__ __launch_bounds__(256) void gemm_rows_kernel() {
    __shared__ float aS[2 * ABUF];
    __shared__ float bS[2 * BBUF];
    const int n0 = blockIdx.x * 64;
    const int i0 = blockIdx.y * 64;
    GemmFrag fr;
    gemm_tile64<DF>(g_ft, DF, g_wbig, RSTRIDE, i0, n0, aS, bS, fr);

    const int tid = threadIdx.x;
    const int lane = tid & 31, warp = tid >> 5;
    const int wm = warp & 1, wn = warp >> 1;
    const int ar = wm * 32 + (lane >> 2);
#pragma unroll
    for (int mt = 0; mt < 2; mt++) {
        int r = i0 + ar + mt * 16;
#pragma unroll
        for (int nf = 0; nf < 2; nf++) {
            int gc = n0 + wn * 16 + nf * 8 + 2 * (lane & 3);
            *(float2*)(g_rows + (size_t)r * RSTRIDE + gc) =
                make_float2(fr.acc[mt][nf][0], fr.acc[mt][nf][1]);
            *(float2*)(g_rows + (size_t)(r + 8) * RSTRIDE + gc) =
                make_float2(fr.acc[mt][nf][2], fr.acc[mt][nf][3]);
        }
    }
}

__global__ __launch_bounds__(256) void gemm_single_kernel(
    const float* __restrict__ ts_b2, float* __restrict__ out) {
    __shared__ float aS[2 * ABUF];
    __shared__ float bS[2 * BBUF];
    const int n0 = blockIdx.x * 64;
    const int i0 = blockIdx.y * 64;
    GemmFrag fr;
    gemm_tile64<512>(g_uln, 512, g_w4t, 384, i0, n0, aS, bS, fr);

    const int tid = threadIdx.x;
    const int lane = tid & 31, warp = tid >> 5;
    const int wm = warp & 1, wn = warp >> 1;
    const int ar = wm * 32 + (lane >> 2);
#pragma unroll
    for (int mt = 0; mt < 2; mt++) {
        int r = i0 + ar + mt * 16;
#pragma unroll
        for (int nf = 0; nf < 2; nf++) {
            int gc = n0 + wn * 16 + nf * 8 + 2 * (lane & 3);
            float bx = ts_b2[gc], by = ts_b2[gc + 1];
            *(float2*)(out + OUT_SINGLE + (size_t)r * 384 + gc) =
                make_float2(fr.acc[mt][nf][0] + bx, fr.acc[mt][nf][1] + by);
            *(float2*)(out + OUT_SINGLE + (size_t)(r + 8) * 384 + gc) =
                make_float2(fr.acc[mt][nf][2] + bx, fr.acc[mt][nf][3] + by);
        }
    }
}

// ---------------------------------------------------------------------------
// post_rows: per-row LN + small heads + uln production. 384 blocks.
// ---------------------------------------------------------------------------
__global__ __launch_bounds__(256) void post_rows_kernel(
    const float* __restrict__ sp_b, const float* __restrict__ sp_g,
    const float* __restrict__ sp_be,
    const float* __restrict__ dms_w1, const float* __restrict__ dms_b1,
    const float* __restrict__ dms_w2, const float* __restrict__ dms_b2,
    const float* __restrict__ sh_w1, const float* __restrict__ sh_b1,
    const float* __restrict__ sh_w2, const float* __restrict__ sh_b2,
    const float* __restrict__ ts_b1, const float* __restrict__ ts_g,
    const float* __restrict__ ts_be,
    float* __restrict__ out)
{
    __shared__ float sS[320];
    __shared__ float red[16];
    __shared__ float mv[2];

    const int i = blockIdx.x, tid = threadIdx.x;
    const float* rowp = g_rows + (size_t)i * RSTRIDE;

    float psum = 0.f, psq = 0.f;
    for (int c = tid; c < 320; c += 256) {
        float v = fmaxf(rowp[c] + sp_b[c], 0.f);
        sS[c] = v;
        psum += v;
        psq += v * v;
    }
    block_stats(psum, psq, 320.f, red, mv);
    {
        float m = mv[0], r = mv[1];
        for (int c = tid; c < 320; c += 256)
            sS[c] = (sS[c] - m) * r * sp_g[c] + sp_be[c];
    }
    __syncthreads();

    {
        float p = 0.f;
        if (tid < 160) {
            float acc = dms_b1[tid];
#pragma unroll 8
            for (int k = 0; k < 320; k++) acc = fmaf(sS[k], dms_w1[k * 160 + tid], acc);
            p = fmaxf(acc, 0.f) * dms_w2[tid];
        }
        float dsum = block_sum(p, red);
        if (tid == 0) {
            float v = dsum + dms_b2[0];
            g_d[i] = v;
            out[OUT_DMS + i] = v;
        }
    }
    __syncthreads();

    {
        float p = 0.f;
        if (tid < 160) {
            float acc = sh_b1[tid];
#pragma unroll 8
            for (int k = 0; k < 320; k++) acc = fmaf(sS[k], sh_w1[k * 160 + tid], acc);
            p = fmaxf(acc, 0.f) * sh_w2[tid];
        }
        float ssum = block_sum(p, red);
        if (tid == 0) {
            float v = ssum + sh_b2[0];
            g_s[i] = v;
            out[OUT_SHAPE + i] = v;
        }
    }

    float u0 = fmaxf(rowp[U_OFF + tid] + ts_b1[tid], 0.f);
    float u1 = fmaxf(rowp[U_OFF + tid + 256] + ts_b1[tid + 256], 0.f);
    psum = u0 + u1;
    psq = u0 * u0 + u1 * u1;
    block_stats(psum, psq, 512.f, red, mv);
    {
        float m = mv[0], r = mv[1];
        g_uln[(size_t)i * 512 + tid] =
            __uint_as_float(tf32r((u0 - m) * r * ts_g[tid] + ts_be[tid]));
        g_uln[(size_t)i * 512 + tid + 256] =
            __uint_as_float(tf32r((u1 - m) * r * ts_g[tid + 256] + ts_be[tid + 256]));
    }
}

// ---------------------------------------------------------------------------
// pair kernel: fp16 m16n8k16 HMMA. M=64 j-tile, 512 threads (16 warps),
// warp grid 2M x 8N (warp tile 32x32 GEMM1, 32x16 GEMM2).
// smem floats: mv[128] | hiS[512] | wcS[2048] | gS[512] | beS[512] | b2S[256]
//   | b3S[128] | hA half2[64][260] (16640) | Wt 2 x [256][36] u32 (18432)
// ---------------------------------------------------------------------------
#define PK_MV  0
#define PK_HIS 128
#define PK_WCS 640
#define PK_GS  2688
#define PK_BES 3200
#define PK_B2S 3712
#define PK_B3S 3968
#define PK_HA  4096    // uint32 view, stride 260 per row
#define PK_WT  20736   // uint32 view, 2 buffers of 256*36
#define PK_FLOATS 39168
#define PK_BYTES (PK_FLOATS * 4)

#define HA_STRIDE 260
#define H2_STRIDE 132
#define WT1BUF (256 * 36)
#define WT2BUF (128 * 36)

__global__ __launch_bounds__(512, 1) void pair_kernel(
    const float* __restrict__ tp_w1, const float* __restrict__ tp_b1,
    const float* __restrict__ tp_g, const float* __restrict__ tp_be,
    const float* __restrict__ tp_b2, const float* __restrict__ tp_b3,
    float* __restrict__ out)
{
    extern __shared__ float sm[];
    uint32_t* hA = (uint32_t*)(sm + PK_HA);
    uint32_t* Wt = (uint32_t*)(sm + PK_WT);

    const int i = blockIdx.y;
    const int j0 = blockIdx.x * 64;
    const int tid = threadIdx.x;
    const int lane = tid & 31, warp = tid >> 5;
    const int wm = warp & 1, wn = warp >> 1;   // 2M x 8N

    // prefetch W2 chunk 0 (cols 0..255, k2 0..31) into Wt buf0
    {
        const uint32_t* src = (const uint32_t*)g_w2h;
        for (int t = tid; t < 2048; t += 512) {
            int n = t >> 3, q = t & 7;
            cpasync16(Wt + n * 36 + q * 4, src + n * 256 + q * 4);
        }
        cpcommit();
    }

    if (tid < 512) {
        int c = tid;
        sm[PK_HIS + c] = g_rows[(size_t)i * RSTRIDE + HI_OFF + c] + tp_b1[c];
        sm[PK_GS + c]  = tp_g[c];
        sm[PK_BES + c] = tp_be[c];
    }
    for (int c = tid; c < 2048; c += 512) sm[PK_WCS + c] = tp_w1[1280 * 512 + c];
    if (tid < 256) sm[PK_B2S + tid] = tp_b2[tid];
    if (tid < 128) sm[PK_B3S + tid] = tp_b3[tid];
    __syncthreads();

    // ---- stage A pass 1: stats (recompute, no store). 8 threads per row. ----
    const int jj = tid >> 3, sub = tid & 7;
    const int j = j0 + jj;
    const float di = g_d[i], si = g_s[i];
    const float dj = g_d[j], sj = g_s[j];
    const float c0 = di - dj, c1 = di * dj, c2 = si - sj, c3 = si * sj;
    const float4* hj4 = (const float4*)(g_rows + (size_t)j * RSTRIDE + HJ_OFF);

    float psum = 0.f, psq = 0.f;
#pragma unroll 4
    for (int cc = 0; cc < 16; cc++) {
        int q = sub + 8 * cc;
        float4 v4 = hj4[q];
        int c = q * 4;
        float vin[4] = {v4.x, v4.y, v4.z, v4.w};
#pragma unroll
        for (int e = 0; e < 4; e++) {
            int cx = c + e;
            float v = fmaxf(sm[PK_HIS + cx] + vin[e] + c0 * sm[PK_WCS + cx]
                            + c1 * sm[PK_WCS + 512 + cx] + c2 * sm[PK_WCS + 1024 + cx]
                            + c3 * sm[PK_WCS + 1536 + cx], 0.f);
            psum += v;
            psq += v * v;
        }
    }
    psum += __shfl_down_sync(0xffffffffu, psum, 4, 8);
    psq  += __shfl_down_sync(0xffffffffu, psq, 4, 8);
    psum += __shfl_down_sync(0xffffffffu, psum, 2, 8);
    psq  += __shfl_down_sync(0xffffffffu, psq, 2, 8);
    psum += __shfl_down_sync(0xffffffffu, psum, 1, 8);
    psq  += __shfl_down_sync(0xffffffffu, psq, 1, 8);
    if (sub == 0) {
        float m = psum / 512.f;
        float v = psq / 512.f - m * m;
        sm[PK_MV + 2 * jj] = m;
        sm[PK_MV + 2 * jj + 1] = rsqrtf(v + 1e-5f);
    }
    __syncthreads();

    // ---- stage A pass 2: recompute + LN + fp16 -> hA half2 ----
    {
        float m = sm[PK_MV + 2 * jj], r = sm[PK_MV + 2 * jj + 1];
#pragma unroll 4
        for (int cc = 0; cc < 16; cc++) {
            int q = sub + 8 * cc;
            float4 v4 = hj4[q];
            int c = q * 4;
            float vin[4] = {v4.x, v4.y, v4.z, v4.w};
            float o[4];
#pragma unroll
            for (int e = 0; e < 4; e++) {
                int cx = c + e;
                float v = fmaxf(sm[PK_HIS + cx] + vin[e] + c0 * sm[PK_WCS + cx]
                                + c1 * sm[PK_WCS + 512 + cx] + c2 * sm[PK_WCS + 1024 + cx]
                                + c3 * sm[PK_WCS + 1536 + cx], 0.f);
                o[e] = (v - m) * r * sm[PK_GS + cx] + sm[PK_BES + cx];
            }
            __half2 u0 = __floats2half2_rn(o[0], o[1]);
            __half2 u1 = __floats2half2_rn(o[2], o[3]);
            hA[jj * HA_STRIDE + (c >> 1)]     = *(uint32_t*)&u0;
            hA[jj * HA_STRIDE + (c >> 1) + 1] = *(uint32_t*)&u1;
        }
    }
    __syncthreads();

    // ---- GEMM1: h2[64][256] = relu(lnh[64][512] @ W2 + b2); K chunks of 64 ----
    float acc[2][4][4];
#pragma unroll
    for (int mt = 0; mt < 2; mt++)
#pragma unroll
        for (int nf = 0; nf < 4; nf++)
#pragma unroll
            for (int e = 0; e < 4; e++) acc[mt][nf][e] = 0.f;

    const int ar = wm * 32 + (lane >> 2);
    const int lk = lane & 3;
    const int bn = lane >> 2;

    for (int kc = 0; kc < 8; kc++) {
        if (kc < 7) {
            uint32_t* dstB = Wt + ((kc + 1) & 1) * WT1BUF;
            const uint32_t* src = (const uint32_t*)g_w2h + (kc + 1) * 32;
            for (int t = tid; t < 2048; t += 512) {
                int n = t >> 3, q = t & 7;
                cpasync16(dstB + n * 36 + q * 4, src + n * 256 + q * 4);
            }
            cpcommit();
            cpwait<1>();
        } else {
            cpwait<0>();
        }
        __syncthreads();
        const uint32_t* bt = Wt + (kc & 1) * WT1BUF;
#pragma unroll
        for (int s = 0; s < 4; s++) {
            int kg = kc * 32 + s * 8;
            uint32_t a[2][4];
#pragma unroll
            for (int mt = 0; mt < 2; mt++) {
                int r = ar + mt * 16;
                a[mt][0] = hA[r * HA_STRIDE + kg + lk];
                a[mt][1] = hA[(r + 8) * HA_STRIDE + kg + lk];
                a[mt][2] = hA[r * HA_STRIDE + kg + 4 + lk];
                a[mt][3] = hA[(r + 8) * HA_STRIDE + kg + 4 + lk];
            }
#pragma unroll
            for (int nf = 0; nf < 4; nf++) {
                int nc = wn * 32 + nf * 8 + bn;
                uint32_t b0 = bt[nc * 36 + s * 8 + lk];
                uint32_t b1 = bt[nc * 36 + s * 8 + 4 + lk];
                mma_f16(acc[0][nf], a[0][0], a[0][1], a[0][2], a[0][3], b0, b1);
                mma_f16(acc[1][nf], a[1][0], a[1][1], a[1][2], a[1][3], b0, b1);
            }
        }
        __syncthreads();
    }

    // prefetch W3 chunk 0 into Wt buf0 (overlaps epilogue1)
    {
        const uint32_t* src = (const uint32_t*)g_w3h;
        for (int t = tid; t < 1024; t += 512) {
            int n = t >> 3, q = t & 7;
            cpasync16(Wt + n * 36 + q * 4, src + n * 128 + q * 4);
        }
        cpcommit();
    }

    // epilogue1: bias + relu + fp16 -> h2 (reuse hA region, stride 132)
    uint32_t* h2 = hA;
    __syncthreads();   // all GEMM1 reads of hA done before overwrite
#pragma unroll
    for (int mt = 0; mt < 2; mt++) {
        int r = ar + mt * 16;
#pragma unroll
        for (int nf = 0; nf < 4; nf++) {
            int cb = wn * 32 + nf * 8 + 2 * lk;
            float x0 = fmaxf(acc[mt][nf][0] + sm[PK_B2S + cb], 0.f);
            float y0 = fmaxf(acc[mt][nf][1] + sm[PK_B2S + cb + 1], 0.f);
            float x1 = fmaxf(acc[mt][nf][2] + sm[PK_B2S + cb], 0.f);
            float y1 = fmaxf(acc[mt][nf][3] + sm[PK_B2S + cb + 1], 0.f);
            __half2 p0 = __floats2half2_rn(x0, y0);
            __half2 p1 = __floats2half2_rn(x1, y1);
            h2[r * H2_STRIDE + (cb >> 1)]       = *(uint32_t*)&p0;
            h2[(r + 8) * H2_STRIDE + (cb >> 1)] = *(uint32_t*)&p1;
        }
    }
    __syncthreads();

    // ---- GEMM2: pair[64][128] = h2[64][256] @ W3 + b3; K chunks of 64 ----
    float acc2[2][2][4];
#pragma unroll
    for (int mt = 0; mt < 2; mt++)
#pragma unroll
        for (int nf = 0; nf < 2; nf++)
#pragma unroll
            for (int e = 0; e < 4; e++) acc2[mt][nf][e] = 0.f;

    for (int kc = 0; kc < 4; kc++) {
        if (kc < 3) {
            uint32_t* dstB = Wt + ((kc + 1) & 1) * WT2BUF;
            const uint32_t* src = (const uint32_t*)g_w3h + (kc + 1) * 32;
            for (int t = tid; t < 1024; t += 512) {
                int n = t >> 3, q = t & 7;
                cpasync16(dstB + n * 36 + q * 4, src + n * 128 + q * 4);
            }
            cpcommit();
            cpwait<1>();
        } else {
            cpwait<0>();
        }
        __syncthreads();
        const uint32_t* bt = Wt + (kc & 1) * WT2BUF;
#pragma unroll
        for (int s = 0; s < 4; s++) {
            int kg = kc * 32 + s * 8;
            uint32_t a[2][4];
#pragma unroll
            for (int mt = 0; mt < 2; mt++) {
                int r = ar + mt * 16;
                a[mt][0] = h2[r * H2_STRIDE + kg + lk];
                a[mt][1] = h2[(r + 8) * H2_STRIDE + kg + lk];
                a[mt][2] = h2[r * H2_STRIDE + kg + 4 + lk];
                a[mt][3] = h2[(r + 8) * H2_STRIDE + kg + 4 + lk];
            }
#pragma unroll
            for (int nf = 0; nf < 2; nf++) {
                int nc = wn * 16 + nf * 8 + bn;
                uint32_t b0 = bt[nc * 36 + s * 8 + lk];
                uint32_t b1 = bt[nc * 36 + s * 8 + 4 + lk];
                mma_f16(acc2[0][nf], a[0][0], a[0][1], a[0][2], a[0][3], b0, b1);
                mma_f16(acc2[1][nf], a[1][0], a[1][1], a[1][2], a[1][3], b0, b1);
            }
        }
        __syncthreads();
    }

    // epilogue2: bias + store
#pragma unroll
    for (int mt = 0; mt < 2; mt++) {
        int r = ar + mt * 16;
#pragma unroll
        for (int nf = 0; nf < 2; nf++) {
            int cb = wn * 16 + nf * 8 + 2 * lk;
            float2 v0, v1;
            v0.x = acc2[mt][nf][0] + sm[PK_B3S + cb];
            v0.y = acc2[mt][nf][1] + sm[PK_B3S + cb + 1];
            v1.x = acc2[mt][nf][2] + sm[PK_B3S + cb];
            v1.y = acc2[mt][nf][3] + sm[PK_B3S + cb + 1];
            size_t base0 = (size_t)OUT_PAIR + ((size_t)i * 384 + j0 + r) * 128 + cb;
            size_t base1 = (size_t)OUT_PAIR + ((size_t)i * 384 + j0 + r + 8) * 128 + cb;
            *(float2*)(out + base0) = v0;
            *(float2*)(out + base1) = v1;
        }
    }
}

extern "C" void kernel_launch(void* const* d_in, const int* in_sizes, int n_in,
                              void* d_out, int out_size) {
    const float* feat   = (const float*)d_in[0];
    const float* sp_w   = (const float*)d_in[1];
    const float* sp_b   = (const float*)d_in[2];
    const float* sp_g   = (const float*)d_in[3];
    const float* sp_be  = (const float*)d_in[4];
    const float* dms_w1 = (const float*)d_in[5];
    const float* dms_b1 = (const float*)d_in[6];
    const float* dms_w2 = (const float*)d_in[7];
    const float* dms_b2 = (const float*)d_in[8];
    const float* sh_w1  = (const float*)d_in[9];
    const float* sh_b1  = (const float*)d_in[10];
    const float* sh_w2  = (const float*)d_in[11];
    const float* sh_b2  = (const float*)d_in[12];
    const float* ts_w1  = (const float*)d_in[13];
    const float* ts_b1  = (const float*)d_in[14];
    const float* ts_g   = (const float*)d_in[15];
    const float* ts_be  = (const float*)d_in[16];
    const float* ts_w2  = (const float*)d_in[17];
    const float* ts_b2  = (const float*)d_in[18];
    const float* tp_w1  = (const float*)d_in[19];
    const float* tp_b1  = (const float*)d_in[20];
    const float* tp_g   = (const float*)d_in[21];
    const float* tp_be  = (const float*)d_in[22];
    const float* tp_w2  = (const float*)d_in[23];
    const float* tp_b2  = (const float*)d_in[24];
    const float* tp_w3  = (const float*)d_in[25];
    const float* tp_b3  = (const float*)d_in[26];
    float* out = (float*)d_out;

    cudaFuncSetAttribute(pair_kernel,
                         cudaFuncAttributeMaxDynamicSharedMemorySize,
                         PK_BYTES);

    prep_kernel<<<256, 256>>>(feat, sp_w, ts_w1, ts_w2, tp_w1, tp_w2, tp_w3);

    gemm_rows_kernel<<<dim3(RSTRIDE / 64, LSEQ / 64), 256>>>();

    post_rows_kernel<<<LSEQ, 256>>>(sp_b, sp_g, sp_be,
                                    dms_w1, dms_b1, dms_w2, dms_b2,
                                    sh_w1, sh_b1, sh_w2, sh_b2,
                                    ts_b1, ts_g, ts_be, out);

    // pair as 4th launch (ncu profiling slot)
    pair_kernel<<<dim3(6, LSEQ), 512, PK_BYTES>>>(
        tp_w1, tp_b1, tp_g, tp_be, tp_b2, tp_b3, out);

    gemm_single_kernel<<<dim3(384 / 64, LSEQ / 64), 256>>>(ts_b2, out);
}

// round 15
// speedup vs baseline: 1.6734x; 1.0223x over previous
#include <cuda_runtime.h>
#include <cuda_fp16.h>
#include <math.h>
#include <stdint.h>

#define LSEQ 384
#define DF 640

// Output packing: single(384*384) | pair(384*384*128) | dms(384) | shape(384)
#define OUT_SINGLE 0
#define OUT_PAIR   147456
#define OUT_DMS    19021824
#define OUT_SHAPE  19022208

// rows GEMM output columns: x1(0..319) | u(320..831) | hi(832..1343) | hj(1344..1855)
#define RSTRIDE 1856
#define U_OFF   320
#define HI_OFF  832
#define HJ_OFF  1344

__device__ float g_d[LSEQ];
__device__ float g_s[LSEQ];
__device__ __align__(16) float g_rows[LSEQ * RSTRIDE];
__device__ __align__(16) float g_uln[LSEQ * 512];
__device__ __align__(16) float g_ft[LSEQ * DF];
__device__ __align__(16) float g_wbig[DF * RSTRIDE];
__device__ __align__(16) float g_w4t[512 * 384];
// fp16 transposed pair weights: [N][K], half2 = adjacent K pair (m16n8k16 B frag)
__device__ __align__(16) __half g_w2h[256 * 512];
__device__ __align__(16) __half g_w3h[128 * 256];

// ---------------------------------------------------------------------------
// helpers
// ---------------------------------------------------------------------------
__device__ __forceinline__ uint32_t tf32r(float x) {
    uint32_t y;
    asm("cvt.rna.tf32.f32 %0, %1;" : "=r"(y) : "f"(x));
    return y;
}

__device__ __forceinline__ void mma_tf32(float* d, uint32_t a0, uint32_t a1,
                                         uint32_t a2, uint32_t a3,
                                         uint32_t b0, uint32_t b1) {
    asm volatile(
        "mma.sync.aligned.m16n8k8.row.col.f32.tf32.tf32.f32 "
        "{%0,%1,%2,%3}, {%4,%5,%6,%7}, {%8,%9}, {%0,%1,%2,%3};"
        : "+f"(d[0]), "+f"(d[1]), "+f"(d[2]), "+f"(d[3])
        : "r"(a0), "r"(a1), "r"(a2), "r"(a3), "r"(b0), "r"(b1));
}

// fp16 m16n8k16, fp32 accumulate
__device__ __forceinline__ void mma_f16(float* d, uint32_t a0, uint32_t a1,
                                        uint32_t a2, uint32_t a3,
                                        uint32_t b0, uint32_t b1) {
    asm volatile(
        "mma.sync.aligned.m16n8k16.row.col.f32.f16.f16.f32 "
        "{%0,%1,%2,%3}, {%4,%5,%6,%7}, {%8,%9}, {%0,%1,%2,%3};"
        : "+f"(d[0]), "+f"(d[1]), "+f"(d[2]), "+f"(d[3])
        : "r"(a0), "r"(a1), "r"(a2), "r"(a3), "r"(b0), "r"(b1));
}

__device__ __forceinline__ void ldsm_x4(uint32_t& r0, uint32_t& r1,
                                        uint32_t& r2, uint32_t& r3, uint32_t addr) {
    asm volatile("ldmatrix.sync.aligned.m8n8.x4.shared.b16 {%0,%1,%2,%3}, [%4];"
                 : "=r"(r0), "=r"(r1), "=r"(r2), "=r"(r3) : "r"(addr));
}

__device__ __forceinline__ void cpasync16(void* dst, const void* src) {
    uint32_t d = (uint32_t)__cvta_generic_to_shared(dst);
    asm volatile("cp.async.ca.shared.global [%0], [%1], 16;" :: "r"(d), "l"(src));
}
__device__ __forceinline__ void cpcommit() {
    asm volatile("cp.async.commit_group;");
}
template <int N>
__device__ __forceinline__ void cpwait() {
    asm volatile("cp.async.wait_group %0;" :: "n"(N));
}

__device__ __forceinline__ void warp_red2(float& a, float& b) {
#pragma unroll
    for (int o = 16; o; o >>= 1) {
        a += __shfl_down_sync(0xffffffffu, a, o);
        b += __shfl_down_sync(0xffffffffu, b, o);
    }
}

__device__ __forceinline__ void block_stats(float psum, float psq, float n,
                                            volatile float* red, volatile float* mv) {
    warp_red2(psum, psq);
    int w = threadIdx.x >> 5, l = threadIdx.x & 31;
    if (l == 0) { red[w] = psum; red[8 + w] = psq; }
    __syncthreads();
    if (threadIdx.x == 0) {
        float s = 0.f, q = 0.f;
#pragma unroll
        for (int k = 0; k < 8; k++) { s += red[k]; q += red[8 + k]; }
        float m = s / n, v = q / n - m * m;
        mv[0] = m;
        mv[1] = rsqrtf(v + 1e-5f);
    }
    __syncthreads();
}

__device__ __forceinline__ float block_sum(float p, volatile float* red) {
    float z = 0.f;
    warp_red2(p, z);
    int w = threadIdx.x >> 5, l = threadIdx.x & 31;
    if (l == 0) red[w] = p;
    __syncthreads();
    if (threadIdx.x == 0) {
        float s = 0.f;
#pragma unroll
        for (int k = 0; k < 8; k++) s += red[k];
        red[0] = s;
    }
    __syncthreads();
    float s = red[0];
    __syncthreads();
    return s;
}

// ---------------------------------------------------------------------------
// prep: tf32-round rows/single operands; fp16-transpose pair weights
// ---------------------------------------------------------------------------
__global__ void prep_kernel(const float* __restrict__ feat,
                            const float* __restrict__ sp_w,
                            const float* __restrict__ ts_w1,
                            const float* __restrict__ ts_w2,
                            const float* __restrict__ tp_w1,
                            const float* __restrict__ tp_w2,
                            const float* __restrict__ tp_w3) {
    const int NF  = LSEQ * DF;
    const int NSP = DF * 320;
    const int NT1 = DF * 512;
    const int NWA = DF * 512;
    const int NWB = DF * 512;
    const int NT2 = 512 * 384;
    const int N2  = 512 * 256;
    const int N3  = 256 * 128;
    const int TOT = NF + NSP + NT1 + NWA + NWB + NT2 + N2 + N3;

    for (int t = blockIdx.x * blockDim.x + threadIdx.x; t < TOT;
         t += gridDim.x * blockDim.x) {
        int u = t;
        if (u < NF) { g_ft[u] = __uint_as_float(tf32r(feat[u])); continue; }
        u -= NF;
        if (u < NSP) {
            int k = u / 320, n = u % 320;
            g_wbig[k * RSTRIDE + n] = __uint_as_float(tf32r(sp_w[u]));
            continue;
        }
        u -= NSP;
        if (u < NT1) {
            int k = u / 512, n = u % 512;
            g_wbig[k * RSTRIDE + U_OFF + n] = __uint_as_float(tf32r(ts_w1[u]));
            continue;
        }
        u -= NT1;
        if (u < NWA) {
            int k = u / 512, n = u % 512;
            g_wbig[k * RSTRIDE + HI_OFF + n] = __uint_as_float(tf32r(tp_w1[u]));
            continue;
        }
        u -= NWA;
        if (u < NWB) {
            int k = u / 512, n = u % 512;
            g_wbig[k * RSTRIDE + HJ_OFF + n] = __uint_as_float(tf32r(tp_w1[(DF + k) * 512 + n]));
            continue;
        }
        u -= NWB;
        if (u < NT2) { g_w4t[u] = __uint_as_float(tf32r(ts_w2[u])); continue; }
        u -= NT2;
        if (u < N2) {
            int k = u / 256, n = u % 256;
            g_w2h[n * 512 + k] = __float2half_rn(tp_w2[u]);
            continue;
        }
        u -= N2;
        {
            int k = u / 128, n = u % 128;
            g_w3h[n * 256 + k] = __float2half_rn(tp_w3[u]);
        }
    }
}

// ---------------------------------------------------------------------------
// generic 64x64-tile tf32 GEMM body (used by gemm_rows/gemm_single)
// ---------------------------------------------------------------------------
#define GPADA 36
#define GPADB 72
#define ABUF (64 * GPADA)
#define BBUF (32 * GPADB)

struct GemmFrag { float acc[2][2][4]; };

template <int KDIM>
__device__ __forceinline__ void gemm_tile64(const float* __restrict__ Asrc, int lda,
                                            const float* __restrict__ Bsrc, int ldb,
                                            int i0, int n0,
                                            float* aS, float* bS, GemmFrag& fr) {
    const int tid = threadIdx.x;
    const int lane = tid & 31, warp = tid >> 5;
    const int wm = warp & 1, wn = warp >> 1;
    const int ar = wm * 32 + (lane >> 2);
    const int ak = lane & 3;
    const int bk = lane & 3;
    const int bn = lane >> 2;
    constexpr int NKB = KDIM / 32;

#pragma unroll
    for (int mt = 0; mt < 2; mt++)
#pragma unroll
        for (int nf = 0; nf < 2; nf++)
#pragma unroll
            for (int e = 0; e < 4; e++) fr.acc[mt][nf][e] = 0.f;

    for (int t = tid; t < 512; t += 256) {
        int r = t >> 3, c4 = t & 7;
        cpasync16(aS + r * GPADA + c4 * 4, Asrc + (size_t)(i0 + r) * lda + c4 * 4);
    }
    for (int t = tid; t < 512; t += 256) {
        int r = t >> 4, c4 = t & 15;
        cpasync16(bS + r * GPADB + c4 * 4, Bsrc + (size_t)r * ldb + n0 + c4 * 4);
    }
    cpcommit();

    for (int kb = 0; kb < NKB; kb++) {
        if (kb + 1 < NKB) {
            float* aD = aS + ((kb + 1) & 1) * ABUF;
            float* bD = bS + ((kb + 1) & 1) * BBUF;
            const float* aG = Asrc + (kb + 1) * 32;
            const float* bG = Bsrc + (size_t)(kb + 1) * 32 * ldb;
            for (int t = tid; t < 512; t += 256) {
                int r = t >> 3, c4 = t & 7;
                cpasync16(aD + r * GPADA + c4 * 4, aG + (size_t)(i0 + r) * lda + c4 * 4);
            }
            for (int t = tid; t < 512; t += 256) {
                int r = t >> 4, c4 = t & 15;
                cpasync16(bD + r * GPADB + c4 * 4, bG + (size_t)r * ldb + n0 + c4 * 4);
            }
            cpcommit();
            cpwait<1>();
        } else {
            cpwait<0>();
        }
        __syncthreads();
        const float* at = aS + (kb & 1) * ABUF;
        const float* bt = bS + (kb & 1) * BBUF;
#pragma unroll
        for (int k8 = 0; k8 < 4; k8++) {
            int kg = k8 * 8;
            uint32_t a[2][4];
#pragma unroll
            for (int mt = 0; mt < 2; mt++) {
                int r = ar + mt * 16;
                a[mt][0] = __float_as_uint(at[r * GPADA + kg + ak]);
                a[mt][1] = __float_as_uint(at[(r + 8) * GPADA + kg + ak]);
                a[mt][2] = __float_as_uint(at[r * GPADA + kg + ak + 4]);
                a[mt][3] = __float_as_uint(at[(r + 8) * GPADA + kg + ak + 4]);
            }
#pragma unroll
            for (int nf = 0; nf < 2; nf++) {
                int nc = wn * 16 + nf * 8 + bn;
                uint32_t b0 = __float_as_uint(bt[(kg + bk) * GPADB + nc]);
                uint32_t b1 = __float_as_uint(bt[(kg + bk + 4) * GPADB + nc]);
                mma_tf32(fr.acc[0][nf], a[0][0], a[0][1], a[0][2], a[0][3], b0, b1);
                mma_tf32(fr.acc[1][nf], a[1][0], a[1][1], a[1][2], a[1][3], b0, b1);
            }
        }
        __syncthreads();
    }
}

__global__ __launch_bounds__(256) void gemm_rows_kernel() {
    __shared__ float aS[2 * ABUF];
    __shared__ float bS[2 * BBUF];
    const int n0 = blockIdx.x * 64;
    const int i0 = blockIdx.y * 64;
    GemmFrag fr;
    gemm_tile64<DF>(g_ft, DF, g_wbig, RSTRIDE, i0, n0, aS, bS, fr);

    const int tid = threadIdx.x;
    const int lane = tid & 31, warp = tid >> 5;
    const int wm = warp & 1, wn = warp >> 1;
    const int ar = wm * 32 + (lane >> 2);
#pragma unroll
    for (int mt = 0; mt < 2; mt++) {
        int r = i0 + ar + mt * 16;
#pragma unroll
        for (int nf = 0; nf < 2; nf++) {
            int gc = n0 + wn * 16 + nf * 8 + 2 * (lane & 3);
            *(float2*)(g_rows + (size_t)r * RSTRIDE + gc) =
                make_float2(fr.acc[mt][nf][0], fr.acc[mt][nf][1]);
            *(float2*)(g_rows + (size_t)(r + 8) * RSTRIDE + gc) =
                make_float2(fr.acc[mt][nf][2], fr.acc[mt][nf][3]);
        }
    }
}

__global__ __launch_bounds__(256) void gemm_single_kernel(
    const float* __restrict__ ts_b2, float* __restrict__ out) {
    __shared__ float aS[2 * ABUF];
    __shared__ float bS[2 * BBUF];
    const int n0 = blockIdx.x * 64;
    const int i0 = blockIdx.y * 64;
    GemmFrag fr;
    gemm_tile64<512>(g_uln, 512, g_w4t, 384, i0, n0, aS, bS, fr);

    const int tid = threadIdx.x;
    const int lane = tid & 31, warp = tid >> 5;
    const int wm = warp & 1, wn = warp >> 1;
    const int ar = wm * 32 + (lane >> 2);
#pragma unroll
    for (int mt = 0; mt < 2; mt++) {
        int r = i0 + ar + mt * 16;
#pragma unroll
        for (int nf = 0; nf < 2; nf++) {
            int gc = n0 + wn * 16 + nf * 8 + 2 * (lane & 3);
            float bx = ts_b2[gc], by = ts_b2[gc + 1];
            *(float2*)(out + OUT_SINGLE + (size_t)r * 384 + gc) =
                make_float2(fr.acc[mt][nf][0] + bx, fr.acc[mt][nf][1] + by);
            *(float2*)(out + OUT_SINGLE + (size_t)(r + 8) * 384 + gc) =
                make_float2(fr.acc[mt][nf][2] + bx, fr.acc[mt][nf][3] + by);
        }
    }
}

// ---------------------------------------------------------------------------
// post_rows: per-row LN + small heads + uln production. 384 blocks.
// ---------------------------------------------------------------------------
__global__ __launch_bounds__(256) void post_rows_kernel(
    const float* __restrict__ sp_b, const float* __restrict__ sp_g,
    const float* __restrict__ sp_be,
    const float* __restrict__ dms_w1, const float* __restrict__ dms_b1,
    const float* __restrict__ dms_w2, const float* __restrict__ dms_b2,
    const float* __restrict__ sh_w1, const float* __restrict__ sh_b1,
    const float* __restrict__ sh_w2, const float* __restrict__ sh_b2,
    const float* __restrict__ ts_b1, const float* __restrict__ ts_g,
    const float* __restrict__ ts_be,
    float* __restrict__ out)
{
    __shared__ float sS[320];
    __shared__ float red[16];
    __shared__ float mv[2];

    const int i = blockIdx.x, tid = threadIdx.x;
    const float* rowp = g_rows + (size_t)i * RSTRIDE;

    float psum = 0.f, psq = 0.f;
    for (int c = tid; c < 320; c += 256) {
        float v = fmaxf(rowp[c] + sp_b[c], 0.f);
        sS[c] = v;
        psum += v;
        psq += v * v;
    }
    block_stats(psum, psq, 320.f, red, mv);
    {
        float m = mv[0], r = mv[1];
        for (int c = tid; c < 320; c += 256)
            sS[c] = (sS[c] - m) * r * sp_g[c] + sp_be[c];
    }
    __syncthreads();

    {
        float p = 0.f;
        if (tid < 160) {
            float acc = dms_b1[tid];
#pragma unroll 8
            for (int k = 0; k < 320; k++) acc = fmaf(sS[k], dms_w1[k * 160 + tid], acc);
            p = fmaxf(acc, 0.f) * dms_w2[tid];
        }
        float dsum = block_sum(p, red);
        if (tid == 0) {
            float v = dsum + dms_b2[0];
            g_d[i] = v;
            out[OUT_DMS + i] = v;
        }
    }
    __syncthreads();

    {
        float p = 0.f;
        if (tid < 160) {
            float acc = sh_b1[tid];
#pragma unroll 8
            for (int k = 0; k < 320; k++) acc = fmaf(sS[k], sh_w1[k * 160 + tid], acc);
            p = fmaxf(acc, 0.f) * sh_w2[tid];
        }
        float ssum = block_sum(p, red);
        if (tid == 0) {
            float v = ssum + sh_b2[0];
            g_s[i] = v;
            out[OUT_SHAPE + i] = v;
        }
    }

    float u0 = fmaxf(rowp[U_OFF + tid] + ts_b1[tid], 0.f);
    float u1 = fmaxf(rowp[U_OFF + tid + 256] + ts_b1[tid + 256], 0.f);
    psum = u0 + u1;
    psq = u0 * u0 + u1 * u1;
    block_stats(psum, psq, 512.f, red, mv);
    {
        float m = mv[0], r = mv[1];
        g_uln[(size_t)i * 512 + tid] =
            __uint_as_float(tf32r((u0 - m) * r * ts_g[tid] + ts_be[tid]));
        g_uln[(size_t)i * 512 + tid + 256] =
            __uint_as_float(tf32r((u1 - m) * r * ts_g[tid + 256] + ts_be[tid + 256]));
    }
}

// ---------------------------------------------------------------------------
// pair kernel: fp16 m16n8k16 HMMA + ldmatrix fragment loads.
// M=64 j-tile, 512 threads (16 warps), warp grid 2M x 8N.
// ---------------------------------------------------------------------------
#define PK_MV  0
#define PK_HIS 128
#define PK_WCS 640
#define PK_GS  2688
#define PK_BES 3200
#define PK_B2S 3712
#define PK_B3S 3968
#define PK_HA  4096    // uint32 view, stride 260 per row
#define PK_WT  20736   // uint32 view, 2 buffers of 256*36
#define PK_FLOATS 39168
#define PK_BYTES (PK_FLOATS * 4)

#define HA_STRIDE 260
#define H2_STRIDE 132
#define WT1BUF (256 * 36)
#define WT2BUF (128 * 36)

__global__ __launch_bounds__(512, 1) void pair_kernel(
    const float* __restrict__ tp_w1, const float* __restrict__ tp_b1,
    const float* __restrict__ tp_g, const float* __restrict__ tp_be,
    const float* __restrict__ tp_b2, const float* __restrict__ tp_b3,
    float* __restrict__ out)
{
    extern __shared__ float sm[];
    uint32_t* hA = (uint32_t*)(sm + PK_HA);
    uint32_t* Wt = (uint32_t*)(sm + PK_WT);
    const uint32_t haB = (uint32_t)__cvta_generic_to_shared(hA);
    const uint32_t wtB = (uint32_t)__cvta_generic_to_shared(Wt);

    const int i = blockIdx.y;
    const int j0 = blockIdx.x * 64;
    const int tid = threadIdx.x;
    const int lane = tid & 31, warp = tid >> 5;
    const int wm = warp & 1, wn = warp >> 1;   // 2M x 8N

    // prefetch W2 chunk 0 into Wt buf0
    {
        const uint32_t* src = (const uint32_t*)g_w2h;
        for (int t = tid; t < 2048; t += 512) {
            int n = t >> 3, q = t & 7;
            cpasync16(Wt + n * 36 + q * 4, src + n * 256 + q * 4);
        }
        cpcommit();
    }

    {
        int c = tid;
        sm[PK_HIS + c] = g_rows[(size_t)i * RSTRIDE + HI_OFF + c] + tp_b1[c];
        sm[PK_GS + c]  = tp_g[c];
        sm[PK_BES + c] = tp_be[c];
    }
    for (int c = tid; c < 2048; c += 512) sm[PK_WCS + c] = tp_w1[1280 * 512 + c];
    if (tid < 256) sm[PK_B2S + tid] = tp_b2[tid];
    if (tid < 128) sm[PK_B3S + tid] = tp_b3[tid];
    __syncthreads();

    // ---- stage A pass 1: stats (recompute, no store). 8 threads per row. ----
    const int jj = tid >> 3, sub = tid & 7;
    const int j = j0 + jj;
    const float di = g_d[i], si = g_s[i];
    const float dj = g_d[j], sj = g_s[j];
    const float c0 = di - dj, c1 = di * dj, c2 = si - sj, c3 = si * sj;
    const float4* hj4 = (const float4*)(g_rows + (size_t)j * RSTRIDE + HJ_OFF);

    float psum = 0.f, psq = 0.f;
#pragma unroll 4
    for (int cc = 0; cc < 16; cc++) {
        int q = sub + 8 * cc;
        float4 v4 = hj4[q];
        int c = q * 4;
        float vin[4] = {v4.x, v4.y, v4.z, v4.w};
#pragma unroll
        for (int e = 0; e < 4; e++) {
            int cx = c + e;
            float v = fmaxf(sm[PK_HIS + cx] + vin[e] + c0 * sm[PK_WCS + cx]
                            + c1 * sm[PK_WCS + 512 + cx] + c2 * sm[PK_WCS + 1024 + cx]
                            + c3 * sm[PK_WCS + 1536 + cx], 0.f);
            psum += v;
            psq += v * v;
        }
    }
    psum += __shfl_down_sync(0xffffffffu, psum, 4, 8);
    psq  += __shfl_down_sync(0xffffffffu, psq, 4, 8);
    psum += __shfl_down_sync(0xffffffffu, psum, 2, 8);
    psq  += __shfl_down_sync(0xffffffffu, psq, 2, 8);
    psum += __shfl_down_sync(0xffffffffu, psum, 1, 8);
    psq  += __shfl_down_sync(0xffffffffu, psq, 1, 8);
    if (sub == 0) {
        float m = psum / 512.f;
        float v = psq / 512.f - m * m;
        sm[PK_MV + 2 * jj] = m;
        sm[PK_MV + 2 * jj + 1] = rsqrtf(v + 1e-5f);
    }
    __syncthreads();

    // ---- stage A pass 2: recompute + LN + fp16 -> hA half2 ----
    {
        float m = sm[PK_MV + 2 * jj], r = sm[PK_MV + 2 * jj + 1];
#pragma unroll 4
        for (int cc = 0; cc < 16; cc++) {
            int q = sub + 8 * cc;
            float4 v4 = hj4[q];
            int c = q * 4;
            float vin[4] = {v4.x, v4.y, v4.z, v4.w};
            float o[4];
#pragma unroll
            for (int e = 0; e < 4; e++) {
                int cx = c + e;
                float v = fmaxf(sm[PK_HIS + cx] + vin[e] + c0 * sm[PK_WCS + cx]
                                + c1 * sm[PK_WCS + 512 + cx] + c2 * sm[PK_WCS + 1024 + cx]
                                + c3 * sm[PK_WCS + 1536 + cx], 0.f);
                o[e] = (v - m) * r * sm[PK_GS + cx] + sm[PK_BES + cx];
            }
            __half2 u0 = __floats2half2_rn(o[0], o[1]);
            __half2 u1 = __floats2half2_rn(o[2], o[3]);
            hA[jj * HA_STRIDE + (c >> 1)]     = *(uint32_t*)&u0;
            hA[jj * HA_STRIDE + (c >> 1) + 1] = *(uint32_t*)&u1;
        }
    }
    __syncthreads();

    // ---- ldmatrix per-lane base addresses ----
    const int mi = lane >> 3, rr = lane & 7;     // matrix idx, row-in-matrix
    // A (GEMM1, stride HA): matrices m0=rows+0/klo, m1=rows+8/klo, m2=+0/khi, m3=+8/khi
    uint32_t aAddr1[2], aAddr2[2];
#pragma unroll
    for (int mt = 0; mt < 2; mt++) {
        int rA = wm * 32 + mt * 16 + (mi & 1) * 8 + rr;
        aAddr1[mt] = haB + (uint32_t)(rA * HA_STRIDE + (mi >> 1) * 4) * 4u;
        aAddr2[mt] = haB + (uint32_t)(rA * H2_STRIDE + (mi >> 1) * 4) * 4u;
    }
    // B GEMM1 (4 nf per s -> 2 x4 pairs): matrices (nf_local = 2p + (mi>>1), khalf = mi&1)
    uint32_t bAddr1[2];
#pragma unroll
    for (int p = 0; p < 2; p++) {
        int nB = wn * 32 + (2 * p + (mi >> 1)) * 8 + rr;
        bAddr1[p] = wtB + (uint32_t)(nB * 36 + (mi & 1) * 4) * 4u;
    }
    // B GEMM2 (2 nf per s -> 1 x4): nf_local = mi>>1
    uint32_t bAddr2;
    {
        int nB = wn * 16 + (mi >> 1) * 8 + rr;
        bAddr2 = wtB + (uint32_t)(nB * 36 + (mi & 1) * 4) * 4u;
    }

    // ---- GEMM1: h2[64][256] = relu(lnh[64][512] @ W2 + b2); K chunks of 64 ----
    float acc[2][4][4];
#pragma unroll
    for (int mt = 0; mt < 2; mt++)
#pragma unroll
        for (int nf = 0; nf < 4; nf++)
#pragma unroll
            for (int e = 0; e < 4; e++) acc[mt][nf][e] = 0.f;

    const int ar = wm * 32 + (lane >> 2);
    const int lk = lane & 3;

    for (int kc = 0; kc < 8; kc++) {
        if (kc < 7) {
            uint32_t* dstB = Wt + ((kc + 1) & 1) * WT1BUF;
            const uint32_t* src = (const uint32_t*)g_w2h + (kc + 1) * 32;
            for (int t = tid; t < 2048; t += 512) {
                int n = t >> 3, q = t & 7;
                cpasync16(dstB + n * 36 + q * 4, src + n * 256 + q * 4);
            }
            cpcommit();
            cpwait<1>();
        } else {
            cpwait<0>();
        }
        __syncthreads();
        const uint32_t wtOff = (uint32_t)((kc & 1) * WT1BUF) * 4u;
#pragma unroll
        for (int s = 0; s < 4; s++) {
            uint32_t aOff = (uint32_t)((kc * 32 + s * 8)) * 4u;
            uint32_t bOff = wtOff + (uint32_t)(s * 8) * 4u;
            uint32_t a[2][4];
            ldsm_x4(a[0][0], a[0][1], a[0][2], a[0][3], aAddr1[0] + aOff);
            ldsm_x4(a[1][0], a[1][1], a[1][2], a[1][3], aAddr1[1] + aOff);
            uint32_t b[2][4];
            ldsm_x4(b[0][0], b[0][1], b[0][2], b[0][3], bAddr1[0] + bOff);
            ldsm_x4(b[1][0], b[1][1], b[1][2], b[1][3], bAddr1[1] + bOff);
#pragma unroll
            for (int p = 0; p < 2; p++) {
                mma_f16(acc[0][2 * p],     a[0][0], a[0][1], a[0][2], a[0][3], b[p][0], b[p][1]);
                mma_f16(acc[1][2 * p],     a[1][0], a[1][1], a[1][2], a[1][3], b[p][0], b[p][1]);
                mma_f16(acc[0][2 * p + 1], a[0][0], a[0][1], a[0][2], a[0][3], b[p][2], b[p][3]);
                mma_f16(acc[1][2 * p + 1], a[1][0], a[1][1], a[1][2], a[1][3], b[p][2], b[p][3]);
            }
        }
        __syncthreads();
    }

    // prefetch W3 chunk 0 into Wt buf0 (overlaps epilogue1)
    {
        const uint32_t* src = (const uint32_t*)g_w3h;
        for (int t = tid; t < 1024; t += 512) {
            int n = t >> 3, q = t & 7;
            cpasync16(Wt + n * 36 + q * 4, src + n * 128 + q * 4);
        }
        cpcommit();
    }

    // epilogue1: bias + relu + fp16 -> h2 (reuse hA region, stride 132)
    uint32_t* h2 = hA;
    __syncthreads();
#pragma unroll
    for (int mt = 0; mt < 2; mt++) {
        int r = ar + mt * 16;
#pragma unroll
        for (int nf = 0; nf < 4; nf++) {
            int cb = wn * 32 + nf * 8 + 2 * lk;
            float x0 = fmaxf(acc[mt][nf][0] + sm[PK_B2S + cb], 0.f);
            float y0 = fmaxf(acc[mt][nf][1] + sm[PK_B2S + cb + 1], 0.f);
            float x1 = fmaxf(acc[mt][nf][2] + sm[PK_B2S + cb], 0.f);
            float y1 = fmaxf(acc[mt][nf][3] + sm[PK_B2S + cb + 1], 0.f);
            __half2 p0 = __floats2half2_rn(x0, y0);
            __half2 p1 = __floats2half2_rn(x1, y1);
            h2[r * H2_STRIDE + (cb >> 1)]       = *(uint32_t*)&p0;
            h2[(r + 8) * H2_STRIDE + (cb >> 1)] = *(uint32_t*)&p1;
        }
    }
    __syncthreads();

    // ---- GEMM2: pair[64][128] = h2[64][256] @ W3 + b3; K chunks of 64 ----
    float acc2[2][2][4];
#pragma unroll
    for (int mt = 0; mt < 2; mt++)
#pragma unroll
        for (int nf = 0; nf < 2; nf++)
#pragma unroll
            for (int e = 0; e < 4; e++) acc2[mt][nf][e] = 0.f;

    for (int kc = 0; kc < 4; kc++) {
        if (kc < 3) {
            uint32_t* dstB = Wt + ((kc + 1) & 1) * WT2BUF;
            const uint32_t* src = (const uint32_t*)g_w3h + (kc + 1) * 32;
            for (int t = tid; t < 1024; t += 512) {
                int n = t >> 3, q = t & 7;
                cpasync16(dstB + n * 36 + q * 4, src + n * 128 + q * 4);
            }
            cpcommit();
            cpwait<1>();
        } else {
            cpwait<0>();
        }
        __syncthreads();
        const uint32_t wtOff = (uint32_t)((kc & 1) * WT2BUF) * 4u;
#pragma unroll
        for (int s = 0; s < 4; s++) {
            uint32_t aOff = (uint32_t)((kc * 32 + s * 8)) * 4u;
            uint32_t bOff = wtOff + (uint32_t)(s * 8) * 4u;
            uint32_t a[2][4];
            ldsm_x4(a[0][0], a[0][1], a[0][2], a[0][3], aAddr2[0] + aOff);
            ldsm_x4(a[1][0], a[1][1], a[1][2], a[1][3], aAddr2[1] + aOff);
            uint32_t b[4];
            ldsm_x4(b[0], b[1], b[2], b[3], bAddr2 + bOff);
            mma_f16(acc2[0][0], a[0][0], a[0][1], a[0][2], a[0][3], b[0], b[1]);
            mma_f16(acc2[1][0], a[1][0], a[1][1], a[1][2], a[1][3], b[0], b[1]);
            mma_f16(acc2[0][1], a[0][0], a[0][1], a[0][2], a[0][3], b[2], b[3]);
            mma_f16(acc2[1][1], a[1][0], a[1][1], a[1][2], a[1][3], b[2], b[3]);
        }
        __syncthreads();
    }

    // epilogue2: bias + store
#pragma unroll
    for (int mt = 0; mt < 2; mt++) {
        int r = ar + mt * 16;
#pragma unroll
        for (int nf = 0; nf < 2; nf++) {
            int cb = wn * 16 + nf * 8 + 2 * lk;
            float2 v0, v1;
            v0.x = acc2[mt][nf][0] + sm[PK_B3S + cb];
            v0.y = acc2[mt][nf][1] + sm[PK_B3S + cb + 1];
            v1.x = acc2[mt][nf][2] + sm[PK_B3S + cb];
            v1.y = acc2[mt][nf][3] + sm[PK_B3S + cb + 1];
            size_t base0 = (size_t)OUT_PAIR + ((size_t)i * 384 + j0 + r) * 128 + cb;
            size_t base1 = (size_t)OUT_PAIR + ((size_t)i * 384 + j0 + r + 8) * 128 + cb;
            *(float2*)(out + base0) = v0;
            *(float2*)(out + base1) = v1;
        }
    }
}

extern "C" void kernel_launch(void* const* d_in, const int* in_sizes, int n_in,
                              void* d_out, int out_size) {
    const float* feat   = (const float*)d_in[0];
    const float* sp_w   = (const float*)d_in[1];
    const float* sp_b   = (const float*)d_in[2];
    const float* sp_g   = (const float*)d_in[3];
    const float* sp_be  = (const float*)d_in[4];
    const float* dms_w1 = (const float*)d_in[5];
    const float* dms_b1 = (const float*)d_in[6];
    const float* dms_w2 = (const float*)d_in[7];
    const float* dms_b2 = (const float*)d_in[8];
    const float* sh_w1  = (const float*)d_in[9];
    const float* sh_b1  = (const float*)d_in[10];
    const float* sh_w2  = (const float*)d_in[11];
    const float* sh_b2  = (const float*)d_in[12];
    const float* ts_w1  = (const float*)d_in[13];
    const float* ts_b1  = (const float*)d_in[14];
    const float* ts_g   = (const float*)d_in[15];
    const float* ts_be  = (const float*)d_in[16];
    const float* ts_w2  = (const float*)d_in[17];
    const float* ts_b2  = (const float*)d_in[18];
    const float* tp_w1  = (const float*)d_in[19];
    const float* tp_b1  = (const float*)d_in[20];
    const float* tp_g   = (const float*)d_in[21];
    const float* tp_be  = (const float*)d_in[22];
    const float* tp_w2  = (const float*)d_in[23];
    const float* tp_b2  = (const float*)d_in[24];
    const float* tp_w3  = (const float*)d_in[25];
    const float* tp_b3  = (const float*)d_in[26];
    float* out = (float*)d_out;

    cudaFuncSetAttribute(pair_kernel,
                         cudaFuncAttributeMaxDynamicSharedMemorySize,
                         PK_BYTES);

    prep_kernel<<<256, 256>>>(feat, sp_w, ts_w1, ts_w2, tp_w1, tp_w2, tp_w3);

    gemm_rows_kernel<<<dim3(RSTRIDE / 64, LSEQ / 64), 256>>>();

    post_rows_kernel<<<LSEQ, 256>>>(sp_b, sp_g, sp_be,
                                    dms_w1, dms_b1, dms_w2, dms_b2,
                                    sh_w1, sh_b1, sh_w2, sh_b2,
                                    ts_b1, ts_g, ts_be, out);

    // pair as 4th launch (ncu profiling slot)
    pair_kernel<<<dim3(6, LSEQ), 512, PK_BYTES>>>(
        tp_w1, tp_b1, tp_g, tp_be, tp_b2, tp_b3, out);

    gemm_single_kernel<<<dim3(384 / 64, LSEQ / 64), 256>>>(ts_b2, out);
}